// round 1
// baseline (speedup 1.0000x reference)
#include <cuda_runtime.h>
#include <cuda_bf16.h>
#include <math.h>

// Problem constants
#define NN   50000
#define EE   800000
#define NMOL 2000
#define INRR 64
#define OUTD 128
#define EDD  16
#define CLSD 256
#define HSW  640   // OUT*(L_CONV+1)

// Static scratch (no allocations allowed)
__device__ float g_agg[(size_t)NN * 128];          // agg buffer (also used as [N,64])
__device__ float g_h0[(size_t)NN * 128];           // conv1 output
__device__ float g_HS[(size_t)NN * HSW];           // concat buffer [N,640]
__device__ float g_pool[(size_t)NMOL * 128];       // per-mol pooled
__device__ float g_z1[(size_t)NN * CLSD];
__device__ float g_z2[(size_t)NN * CLSD];

__device__ __forceinline__ float dleaky(float v) {
    float t = v > 0.f ? v : 0.01f * v;
    return t > 0.f ? t : 0.01f * t;
}
__device__ __forceinline__ float leaky1(float v) {
    return v > 0.f ? v : 0.01f * v;
}

// ---------------------------------------------------------------------------
// Strided row copy: agg[n*D + c] = x[n*ldx + c]   (vectorized float4)
// ---------------------------------------------------------------------------
__global__ void copy_rows_kernel(const float* __restrict__ x, int ldx,
                                 float* __restrict__ agg, int D) {
    int idx = blockIdx.x * blockDim.x + threadIdx.x;
    int perRow = D >> 2;
    int n = idx / perRow;
    if (n >= NN) return;
    int c = (idx - n * perRow) << 2;
    *(float4*)&agg[(size_t)n * D + c] = *(const float4*)&x[(size_t)n * ldx + c];
}

// ---------------------------------------------------------------------------
// Fused edge kernel: per edge e:
//   msg = relu(x[src] + edge_attr[e] @ eW + eb);  agg[dst] += msg (red.v4)
// Warp-per-edge, eW in registers, attr broadcast via shfl.
// ---------------------------------------------------------------------------
template <int D>
__global__ __launch_bounds__(256)
void edge_kernel(const float* __restrict__ attr,
                 const int* __restrict__ src,
                 const int* __restrict__ dstv,
                 const float* __restrict__ x, int ldx,
                 const float* __restrict__ eW,
                 const float* __restrict__ eb,
                 float* __restrict__ agg) {
    constexpr int C = D / 32;                 // cols per lane (2 or 4)
    const int lane = threadIdx.x & 31;
    int w  = (blockIdx.x * blockDim.x + threadIdx.x) >> 5;
    int nw = (gridDim.x * blockDim.x) >> 5;

    float wreg[16 * C];
#pragma unroll
    for (int k = 0; k < 16; k++)
#pragma unroll
        for (int c = 0; c < C; c++)
            wreg[k * C + c] = eW[k * D + lane * C + c];
    float ebr[C];
#pragma unroll
    for (int c = 0; c < C; c++) ebr[c] = eb[lane * C + c];

    for (int e = w; e < EE; e += nw) {
        float a = __ldg(&attr[(size_t)e * 16 + (lane & 15)]);
        float acc[C];
#pragma unroll
        for (int c = 0; c < C; c++) acc[c] = ebr[c];
#pragma unroll
        for (int k = 0; k < 16; k++) {
            float av = __shfl_sync(0xffffffffu, a, k);
#pragma unroll
            for (int c = 0; c < C; c++) acc[c] = fmaf(av, wreg[k * C + c], acc[c]);
        }
        int s = src[e], d = dstv[e];
        const float* xp = x + (size_t)s * ldx + lane * C;
        if (C == 4) {
            float4 xv = *(const float4*)xp;
            float m0 = xv.x + acc[0]; m0 = m0 > 0.f ? m0 : 0.f;
            float m1 = xv.y + acc[1]; m1 = m1 > 0.f ? m1 : 0.f;
            float m2 = xv.z + acc[2]; m2 = m2 > 0.f ? m2 : 0.f;
            float m3 = xv.w + acc[3]; m3 = m3 > 0.f ? m3 : 0.f;
            float* ap = agg + (size_t)d * D + lane * C;
            asm volatile("red.global.add.v4.f32 [%0], {%1,%2,%3,%4};"
                         :: "l"(ap), "f"(m0), "f"(m1), "f"(m2), "f"(m3) : "memory");
        } else {
            float2 xv = *(const float2*)xp;
            float m0 = xv.x + acc[0]; m0 = m0 > 0.f ? m0 : 0.f;
            float m1 = xv.y + acc[1]; m1 = m1 > 0.f ? m1 : 0.f;
            float* ap = agg + (size_t)d * D + lane * C;
            asm volatile("red.global.add.v2.f32 [%0], {%1,%2};"
                         :: "l"(ap), "f"(m0), "f"(m1) : "memory");
        }
    }
}

// ---------------------------------------------------------------------------
// SGEMM: C[N,M] = act( scale(A[N,K] @ B[K,M] + bias) )
//   BN (eval): y = gamma * (y * BN_INV) + beta   (if gamma != nullptr)
//   ACT: 0 = none, 1 = leaky, 2 = double-leaky
// 128x128 tile, BK=8, 256 threads, 8x8 microtile.
// ---------------------------------------------------------------------------
template <int ACT>
__global__ __launch_bounds__(256)
void sgemm_kernel(const float* __restrict__ A, int lda,
                  const float* __restrict__ B,
                  const float* __restrict__ bias,
                  const float* __restrict__ gamma,
                  const float* __restrict__ beta,
                  float* __restrict__ Cmat, int ldc,
                  int Nrows, int K, int M, float bn_inv) {
    __shared__ float As[8][128];
    __shared__ float Bs[8][128];

    const int tid = threadIdx.x;
    const int tx = tid & 15;
    const int ty = tid >> 4;
    const int row0 = blockIdx.y * 128;
    const int col0 = blockIdx.x * 128;

    // A tile load mapping: idx = tid*4 over [128 rows x 8 k]
    const int am = tid >> 1;             // (tid*4)/8
    const int ak = (tid & 1) * 4;        // 0 or 4
    // B tile load mapping: idx = tid*4 over [8 k x 128 m]
    const int bk = tid >> 5;
    const int bm = (tid << 2) & 127;

    float acc[8][8];
#pragma unroll
    for (int i = 0; i < 8; i++)
#pragma unroll
        for (int j = 0; j < 8; j++) acc[i][j] = 0.f;

    for (int k0 = 0; k0 < K; k0 += 8) {
        float4 av = make_float4(0.f, 0.f, 0.f, 0.f);
        int arow = row0 + am;
        if (arow < Nrows)
            av = *(const float4*)&A[(size_t)arow * lda + k0 + ak];
        float4 bv = *(const float4*)&B[(size_t)(k0 + bk) * M + col0 + bm];

        __syncthreads();
        As[ak + 0][am] = av.x;
        As[ak + 1][am] = av.y;
        As[ak + 2][am] = av.z;
        As[ak + 3][am] = av.w;
        *(float4*)&Bs[bk][bm] = bv;
        __syncthreads();

#pragma unroll
        for (int kk = 0; kk < 8; kk++) {
            float ra[8], rb[8];
            float4 a0 = *(const float4*)&As[kk][ty * 8];
            float4 a1 = *(const float4*)&As[kk][ty * 8 + 4];
            ra[0]=a0.x; ra[1]=a0.y; ra[2]=a0.z; ra[3]=a0.w;
            ra[4]=a1.x; ra[5]=a1.y; ra[6]=a1.z; ra[7]=a1.w;
            float4 b0 = *(const float4*)&Bs[kk][tx * 4];
            float4 b1 = *(const float4*)&Bs[kk][64 + tx * 4];
            rb[0]=b0.x; rb[1]=b0.y; rb[2]=b0.z; rb[3]=b0.w;
            rb[4]=b1.x; rb[5]=b1.y; rb[6]=b1.z; rb[7]=b1.w;
#pragma unroll
            for (int i = 0; i < 8; i++)
#pragma unroll
                for (int j = 0; j < 8; j++)
                    acc[i][j] = fmaf(ra[i], rb[j], acc[i][j]);
        }
    }

    // epilogue
#pragma unroll
    for (int i = 0; i < 8; i++) {
        int row = row0 + ty * 8 + i;
        if (row >= Nrows) continue;
#pragma unroll
        for (int j = 0; j < 8; j++) {
            int colLocal = (j < 4) ? (tx * 4 + j) : (64 + tx * 4 + (j - 4));
            int col = col0 + colLocal;
            float v = acc[i][j] + bias[col];
            if (gamma != nullptr)
                v = gamma[col] * (v * bn_inv) + beta[col];
            if (ACT == 1) v = leaky1(v);
            else if (ACT == 2) v = dleaky(v);
            Cmat[(size_t)row * ldc + col] = v;
        }
    }
}

// ---------------------------------------------------------------------------
// Pooling: zero, accumulate (red.v4), broadcast back into HS cols 512:640
// ---------------------------------------------------------------------------
__global__ void zero_pool_kernel() {
    int idx = blockIdx.x * blockDim.x + threadIdx.x;
    if (idx < NMOL * 128 / 4)
        *(float4*)&g_pool[idx * 4] = make_float4(0.f, 0.f, 0.f, 0.f);
}

__global__ void pool_kernel(const int* __restrict__ batch) {
    int idx = blockIdx.x * blockDim.x + threadIdx.x;   // N*32 threads
    int n = idx >> 5;
    if (n >= NN) return;
    int c4 = (idx & 31) << 2;
    float4 v = *(const float4*)&g_HS[(size_t)n * HSW + 384 + c4];
    float* p = g_pool + (size_t)batch[n] * 128 + c4;
    asm volatile("red.global.add.v4.f32 [%0], {%1,%2,%3,%4};"
                 :: "l"(p), "f"(v.x), "f"(v.y), "f"(v.z), "f"(v.w) : "memory");
}

__global__ void bcast_kernel(const int* __restrict__ batch) {
    int idx = blockIdx.x * blockDim.x + threadIdx.x;   // N*32 threads
    int n = idx >> 5;
    if (n >= NN) return;
    int c4 = (idx & 31) << 2;
    float4 v = *(const float4*)&g_pool[(size_t)batch[n] * 128 + c4];
    *(float4*)&g_HS[(size_t)n * HSW + 512 + c4] = v;
}

// ---------------------------------------------------------------------------
// Final: out[n] = sigmoid(Z1[n,:] . fW + fb)
// ---------------------------------------------------------------------------
__global__ void final_kernel(const float* __restrict__ Z,
                             const float* __restrict__ fW,
                             const float* __restrict__ fb,
                             float* __restrict__ out) {
    int idx = blockIdx.x * blockDim.x + threadIdx.x;
    int n = idx >> 5;
    if (n >= NN) return;
    int lane = idx & 31;
    float s = 0.f;
#pragma unroll
    for (int j = lane; j < CLSD; j += 32)
        s = fmaf(Z[(size_t)n * CLSD + j], fW[j], s);
#pragma unroll
    for (int o = 16; o; o >>= 1) s += __shfl_xor_sync(0xffffffffu, s, o);
    if (lane == 0) {
        float z = s + fb[0];
        out[n] = 1.f / (1.f + expf(-z));
    }
}

// ---------------------------------------------------------------------------
// Launch
// ---------------------------------------------------------------------------
extern "C" void kernel_launch(void* const* d_in, const int* in_sizes, int n_in,
                              void* d_out, int out_size) {
    const float* x    = (const float*)d_in[0];
    const int*   ei   = (const int*)d_in[1];
    const float* attr = (const float*)d_in[2];
    const int*   batch= (const int*)d_in[3];
    const float* c1W  = (const float*)d_in[4];
    const float* c1b  = (const float*)d_in[5];
    const float* c1g  = (const float*)d_in[6];
    const float* c1be = (const float*)d_in[7];
    const float* c1eW = (const float*)d_in[8];
    const float* c1eb = (const float*)d_in[9];
    const float* cW   = (const float*)d_in[10];
    const float* cb   = (const float*)d_in[11];
    const float* cg   = (const float*)d_in[12];
    const float* cbe  = (const float*)d_in[13];
    const float* ceW  = (const float*)d_in[14];
    const float* ceb  = (const float*)d_in[15];
    const float* k1W  = (const float*)d_in[16];
    const float* k1b  = (const float*)d_in[17];
    const float* kW   = (const float*)d_in[18];
    const float* kb   = (const float*)d_in[19];
    const float* fW   = (const float*)d_in[20];
    const float* fb   = (const float*)d_in[21];
    float* out = (float*)d_out;

    const int* srcp = ei;
    const int* dstp = ei + EE;

    const float bn_inv = (float)(1.0 / (double)((float)sqrt(1.0 + 1e-5)));

    float *agg, *h0, *HS, *z1, *z2;
    cudaGetSymbolAddress((void**)&agg, g_agg);
    cudaGetSymbolAddress((void**)&h0,  g_h0);
    cudaGetSymbolAddress((void**)&HS,  g_HS);
    cudaGetSymbolAddress((void**)&z1,  g_z1);
    cudaGetSymbolAddress((void**)&z2,  g_z2);

    const int EDGE_BLOCKS = 2368;   // 148 SMs * 16
    dim3 gemmBlock(256);

    // ---- conv1 (64 -> 128) ----
    {
        int threads = NN * (INRR / 4);
        copy_rows_kernel<<<(threads + 255) / 256, 256>>>(x, INRR, agg, INRR);
        edge_kernel<64><<<EDGE_BLOCKS, 256>>>(attr, srcp, dstp, x, INRR, c1eW, c1eb, agg);
        dim3 grid(1, (NN + 127) / 128);
        sgemm_kernel<2><<<grid, gemmBlock>>>(agg, 64, c1W, c1b, c1g, c1be,
                                             h0, 128, NN, 64, 128, bn_inv);
    }

    // ---- conv loop (4 layers, 128 -> 128), outputs into HS cols i*128 ----
    for (int i = 0; i < 4; i++) {
        const float* inPtr = (i == 0) ? h0 : (HS + (size_t)(i - 1) * 128);
        int ldin = (i == 0) ? 128 : HSW;
        int threads = NN * (128 / 4);
        copy_rows_kernel<<<(threads + 255) / 256, 256>>>(inPtr, ldin, agg, 128);
        edge_kernel<128><<<EDGE_BLOCKS, 256>>>(attr, srcp, dstp, inPtr, ldin,
                                               ceW + (size_t)i * EDD * OUTD,
                                               ceb + (size_t)i * OUTD, agg);
        dim3 grid(1, (NN + 127) / 128);
        sgemm_kernel<2><<<grid, gemmBlock>>>(agg, 128,
                                             cW + (size_t)i * OUTD * OUTD,
                                             cb + (size_t)i * OUTD,
                                             cg + (size_t)i * OUTD,
                                             cbe + (size_t)i * OUTD,
                                             HS + (size_t)i * 128, HSW,
                                             NN, 128, 128, bn_inv);
    }

    // ---- global_add_pool of final h (HS col 384) + broadcast into col 512 ----
    zero_pool_kernel<<<(NMOL * 128 / 4 + 255) / 256, 256>>>();
    pool_kernel<<<(NN * 32 + 255) / 256, 256>>>(batch);
    bcast_kernel<<<(NN * 32 + 255) / 256, 256>>>(batch);

    // ---- classifier ----
    {
        dim3 grid1(CLSD / 128, (NN + 127) / 128);
        sgemm_kernel<0><<<grid1, gemmBlock>>>(HS, HSW, k1W, k1b, nullptr, nullptr,
                                              z1, CLSD, NN, HSW, CLSD, bn_inv);
        sgemm_kernel<1><<<grid1, gemmBlock>>>(z1, CLSD, kW, kb, nullptr, nullptr,
                                              z2, CLSD, NN, CLSD, CLSD, bn_inv);
        sgemm_kernel<1><<<grid1, gemmBlock>>>(z2, CLSD, kW + CLSD * CLSD, kb + CLSD,
                                              nullptr, nullptr,
                                              z1, CLSD, NN, CLSD, CLSD, bn_inv);
    }

    // ---- final dot + sigmoid ----
    final_kernel<<<(NN * 32 + 255) / 256, 256>>>(z1, fW, fb, out);
}

// round 2
// speedup vs baseline: 1.2896x; 1.2896x over previous
#include <cuda_runtime.h>
#include <cuda_bf16.h>
#include <math.h>

// Problem constants
#define NN   50000
#define EE   800000
#define NMOL 2000
#define INRR 64
#define OUTD 128
#define EDD  16
#define CLSD 256
#define HSW  640   // OUT*(L_CONV+1)

// Static scratch (no allocations allowed)
__device__ float g_agg[(size_t)NN * 128];          // agg buffer (also used as [N,64])
__device__ float g_h0[(size_t)NN * 128];           // conv1 output
__device__ float g_HS[(size_t)NN * HSW];           // concat buffer [N,640]
__device__ float g_pool[(size_t)NMOL * 128];       // per-mol pooled
__device__ float g_z1[(size_t)NN * CLSD];
__device__ float g_z2[(size_t)NN * CLSD];
// CSR (by dst)
__device__ int g_cnt[NN];
__device__ int g_off[NN + 1];
__device__ int g_cur[NN];
__device__ int g_eid[EE];

__device__ __forceinline__ float dleaky(float v) {
    float t = v > 0.f ? v : 0.01f * v;
    return t > 0.f ? t : 0.01f * t;
}
__device__ __forceinline__ float leaky1(float v) {
    return v > 0.f ? v : 0.01f * v;
}
__device__ __forceinline__ unsigned f2tf(float x) {
    unsigned r;
    asm("cvt.rna.tf32.f32 %0, %1;" : "=r"(r) : "f"(x));
    return r;
}

// ---------------------------------------------------------------------------
// CSR build kernels
// ---------------------------------------------------------------------------
__global__ void csr_zero_kernel() {
    int i = blockIdx.x * blockDim.x + threadIdx.x;
    if (i < NN) g_cnt[i] = 0;
}
__global__ void csr_count_kernel(const int* __restrict__ dstv) {
    int e = blockIdx.x * blockDim.x + threadIdx.x;
    if (e < EE) atomicAdd(&g_cnt[dstv[e]], 1);
}
// single block, 1024 threads: exclusive scan of g_cnt -> g_off, g_cur
__global__ void csr_scan_kernel() {
    __shared__ int part[1024];
    const int CH = (NN + 1023) / 1024;   // 49
    int t = threadIdx.x;
    int start = t * CH;
    int sum = 0;
    for (int i = 0; i < CH; i++) {
        int idx = start + i;
        if (idx < NN) sum += g_cnt[idx];
    }
    part[t] = sum;
    __syncthreads();
    // Hillis-Steele inclusive scan
    for (int o = 1; o < 1024; o <<= 1) {
        int v = (t >= o) ? part[t - o] : 0;
        __syncthreads();
        part[t] += v;
        __syncthreads();
    }
    int run = part[t] - sum;  // exclusive prefix of this chunk
    for (int i = 0; i < CH; i++) {
        int idx = start + i;
        if (idx < NN) {
            g_off[idx] = run;
            g_cur[idx] = run;
            run += g_cnt[idx];
        }
    }
    if (t == 0) g_off[NN] = EE;
}
__global__ void csr_fill_kernel(const int* __restrict__ dstv) {
    int e = blockIdx.x * blockDim.x + threadIdx.x;
    if (e < EE) {
        int pos = atomicAdd(&g_cur[dstv[e]], 1);
        g_eid[pos] = e;
    }
}

// ---------------------------------------------------------------------------
// Gather-based edge aggregation: warp per node.
//   agg[n] = x[n] + sum_{e: dst=n} relu(x[src[e]] + attr[e]@eW + eb)
// eW held in registers, attr broadcast via shfl. No atomics.
// ---------------------------------------------------------------------------
template <int D>
__global__ __launch_bounds__(256)
void gather_kernel(const float* __restrict__ attr,
                   const int* __restrict__ src,
                   const float* __restrict__ x, int ldx,
                   const float* __restrict__ eW,
                   const float* __restrict__ eb,
                   float* __restrict__ agg) {
    constexpr int C = D / 32;                 // cols per lane (2 or 4)
    const int lane = threadIdx.x & 31;
    int n = (blockIdx.x * blockDim.x + threadIdx.x) >> 5;
    if (n >= NN) return;

    float wreg[16 * C];
#pragma unroll
    for (int k = 0; k < 16; k++)
#pragma unroll
        for (int c = 0; c < C; c++)
            wreg[k * C + c] = eW[k * D + lane * C + c];
    float ebr[C];
#pragma unroll
    for (int c = 0; c < C; c++) ebr[c] = eb[lane * C + c];

    float acc[C];
    // self term
    if (C == 4) {
        float4 xv = *(const float4*)&x[(size_t)n * ldx + lane * 4];
        acc[0] = xv.x; acc[1] = xv.y; acc[2] = xv.z; acc[3] = xv.w;
    } else {
        float2 xv = *(const float2*)&x[(size_t)n * ldx + lane * 2];
        acc[0] = xv.x; acc[1] = xv.y;
    }

    int s0 = g_off[n], s1 = g_off[n + 1];
    for (int i = s0; i < s1; i++) {
        int eid = g_eid[i];
        int s = src[eid];
        float a = __ldg(&attr[(size_t)eid * 16 + (lane & 15)]);
        float ecc[C];
#pragma unroll
        for (int c = 0; c < C; c++) ecc[c] = ebr[c];
#pragma unroll
        for (int k = 0; k < 16; k++) {
            float av = __shfl_sync(0xffffffffu, a, k);
#pragma unroll
            for (int c = 0; c < C; c++) ecc[c] = fmaf(av, wreg[k * C + c], ecc[c]);
        }
        if (C == 4) {
            float4 xv = *(const float4*)&x[(size_t)s * ldx + lane * 4];
            float m0 = xv.x + ecc[0]; acc[0] += m0 > 0.f ? m0 : 0.f;
            float m1 = xv.y + ecc[1]; acc[1] += m1 > 0.f ? m1 : 0.f;
            float m2 = xv.z + ecc[2]; acc[2] += m2 > 0.f ? m2 : 0.f;
            float m3 = xv.w + ecc[3]; acc[3] += m3 > 0.f ? m3 : 0.f;
        } else {
            float2 xv = *(const float2*)&x[(size_t)s * ldx + lane * 2];
            float m0 = xv.x + ecc[0]; acc[0] += m0 > 0.f ? m0 : 0.f;
            float m1 = xv.y + ecc[1]; acc[1] += m1 > 0.f ? m1 : 0.f;
        }
    }
    if (C == 4) {
        *(float4*)&g_agg[(size_t)n * D + lane * 4] =
            make_float4(acc[0], acc[1], acc[2], acc[3]);
    } else {
        *(float2*)&g_agg[(size_t)n * D + lane * 2] = make_float2(acc[0], acc[1]);
    }
}

// ---------------------------------------------------------------------------
// 3xTF32 tensor-core GEMM: C[N,M] = act( scale(A[N,K] @ B[K,M] + bias) )
// 128x128 tile, BK=16, 256 threads (8 warps, 2x4), warp tile 64x32,
// mma.sync.m16n8k8 tf32, hi/lo split for fp32-level accuracy.
//   ACT: 0 = none, 1 = leaky, 2 = double-leaky. BN applied if gamma != null.
// ---------------------------------------------------------------------------
__device__ __forceinline__ void mma_tf32(float* acc, const unsigned* a, const unsigned* b) {
    asm volatile(
        "mma.sync.aligned.m16n8k8.row.col.f32.tf32.tf32.f32 "
        "{%0,%1,%2,%3}, {%4,%5,%6,%7}, {%8,%9}, {%0,%1,%2,%3};"
        : "+f"(acc[0]), "+f"(acc[1]), "+f"(acc[2]), "+f"(acc[3])
        : "r"(a[0]), "r"(a[1]), "r"(a[2]), "r"(a[3]), "r"(b[0]), "r"(b[1]));
}

template <int ACT>
__global__ __launch_bounds__(256)
void tf32_gemm(const float* __restrict__ A, int lda,
               const float* __restrict__ B,
               const float* __restrict__ bias,
               const float* __restrict__ gamma,
               const float* __restrict__ beta,
               float* __restrict__ Cmat, int ldc,
               int Nrows, int K, int M, float bn_inv) {
    __shared__ unsigned sAh[128][20];   // [m][k], pad 20
    __shared__ unsigned sAl[128][20];
    __shared__ unsigned sBh[16][136];   // [k][n], pad 136 (8k+n banks distinct)
    __shared__ unsigned sBl[16][136];

    const int tid = threadIdx.x;
    const int lane = tid & 31;
    const int wid = tid >> 5;
    const int wm = (wid & 1) * 64;
    const int wn = (wid >> 1) * 32;
    const int row0 = blockIdx.y * 128;
    const int col0 = blockIdx.x * 128;

    float acc[16][4];
#pragma unroll
    for (int i = 0; i < 16; i++)
#pragma unroll
        for (int j = 0; j < 4; j++) acc[i][j] = 0.f;

    for (int k0 = 0; k0 < K; k0 += 16) {
        // stage global loads in registers
        float4 ga[2], gb[2];
#pragma unroll
        for (int j = 0; j < 2; j++) {
            int idx = j * 256 + tid;
            int m = idx >> 2, kk = (idx & 3) << 2;
            int r = row0 + m;
            ga[j] = make_float4(0.f, 0.f, 0.f, 0.f);
            if (r < Nrows) ga[j] = *(const float4*)&A[(size_t)r * lda + k0 + kk];
            int bk = idx >> 5, bn = (idx & 31) << 2;
            gb[j] = *(const float4*)&B[(size_t)(k0 + bk) * M + col0 + bn];
        }
        __syncthreads();
#pragma unroll
        for (int j = 0; j < 2; j++) {
            int idx = j * 256 + tid;
            int m = idx >> 2, kk = (idx & 3) << 2;
            uint4 hv, lv;
            hv.x = f2tf(ga[j].x); lv.x = f2tf(ga[j].x - __uint_as_float(hv.x));
            hv.y = f2tf(ga[j].y); lv.y = f2tf(ga[j].y - __uint_as_float(hv.y));
            hv.z = f2tf(ga[j].z); lv.z = f2tf(ga[j].z - __uint_as_float(hv.z));
            hv.w = f2tf(ga[j].w); lv.w = f2tf(ga[j].w - __uint_as_float(hv.w));
            *(uint4*)&sAh[m][kk] = hv;
            *(uint4*)&sAl[m][kk] = lv;
            int bk = idx >> 5, bn = (idx & 31) << 2;
            hv.x = f2tf(gb[j].x); lv.x = f2tf(gb[j].x - __uint_as_float(hv.x));
            hv.y = f2tf(gb[j].y); lv.y = f2tf(gb[j].y - __uint_as_float(hv.y));
            hv.z = f2tf(gb[j].z); lv.z = f2tf(gb[j].z - __uint_as_float(hv.z));
            hv.w = f2tf(gb[j].w); lv.w = f2tf(gb[j].w - __uint_as_float(hv.w));
            *(uint4*)&sBh[bk][bn] = hv;
            *(uint4*)&sBl[bk][bn] = lv;
        }
        __syncthreads();

#pragma unroll
        for (int ks = 0; ks < 16; ks += 8) {
            unsigned af[4][4], bfh[4][2], bfl[4][2];
            const int ar = lane >> 2, ak = lane & 3;
#pragma unroll
            for (int i = 0; i < 4; i++) {
                int m = wm + i * 16 + ar;
                af[i][0] = sAh[m][ks + ak];
                af[i][1] = sAh[m + 8][ks + ak];
                af[i][2] = sAh[m][ks + ak + 4];
                af[i][3] = sAh[m + 8][ks + ak + 4];
            }
#pragma unroll
            for (int j = 0; j < 4; j++) {
                int n = wn + j * 8 + (lane >> 2);
                int kb = ks + (lane & 3);
                bfh[j][0] = sBh[kb][n];
                bfh[j][1] = sBh[kb + 4][n];
                bfl[j][0] = sBl[kb][n];
                bfl[j][1] = sBl[kb + 4][n];
            }
#pragma unroll
            for (int i = 0; i < 4; i++)
#pragma unroll
                for (int j = 0; j < 4; j++) mma_tf32(acc[i * 4 + j], af[i], bfh[j]);
#pragma unroll
            for (int i = 0; i < 4; i++)
#pragma unroll
                for (int j = 0; j < 4; j++) mma_tf32(acc[i * 4 + j], af[i], bfl[j]);
            // reload A with lo parts
#pragma unroll
            for (int i = 0; i < 4; i++) {
                int m = wm + i * 16 + ar;
                af[i][0] = sAl[m][ks + ak];
                af[i][1] = sAl[m + 8][ks + ak];
                af[i][2] = sAl[m][ks + ak + 4];
                af[i][3] = sAl[m + 8][ks + ak + 4];
            }
#pragma unroll
            for (int i = 0; i < 4; i++)
#pragma unroll
                for (int j = 0; j < 4; j++) mma_tf32(acc[i * 4 + j], af[i], bfh[j]);
        }
    }

    // epilogue
#pragma unroll
    for (int i = 0; i < 4; i++) {
#pragma unroll
        for (int j = 0; j < 4; j++) {
            int r = row0 + wm + i * 16 + (lane >> 2);
            int c = col0 + wn + j * 8 + (lane & 3) * 2;
            float* ap = acc[i * 4 + j];
#pragma unroll
            for (int h = 0; h < 2; h++) {
                int rr = r + h * 8;
                if (rr >= Nrows) continue;
                float v0 = ap[h * 2 + 0] + bias[c];
                float v1 = ap[h * 2 + 1] + bias[c + 1];
                if (gamma != nullptr) {
                    v0 = gamma[c] * (v0 * bn_inv) + beta[c];
                    v1 = gamma[c + 1] * (v1 * bn_inv) + beta[c + 1];
                }
                if (ACT == 1) { v0 = leaky1(v0); v1 = leaky1(v1); }
                else if (ACT == 2) { v0 = dleaky(v0); v1 = dleaky(v1); }
                *(float2*)&Cmat[(size_t)rr * ldc + c] = make_float2(v0, v1);
            }
        }
    }
}

// ---------------------------------------------------------------------------
// Pooling: zero, accumulate (red.v4), broadcast back into HS cols 512:640
// ---------------------------------------------------------------------------
__global__ void zero_pool_kernel() {
    int idx = blockIdx.x * blockDim.x + threadIdx.x;
    if (idx < NMOL * 128 / 4)
        *(float4*)&g_pool[idx * 4] = make_float4(0.f, 0.f, 0.f, 0.f);
}

__global__ void pool_kernel(const int* __restrict__ batch) {
    int idx = blockIdx.x * blockDim.x + threadIdx.x;   // N*32 threads
    int n = idx >> 5;
    if (n >= NN) return;
    int c4 = (idx & 31) << 2;
    float4 v = *(const float4*)&g_HS[(size_t)n * HSW + 384 + c4];
    float* p = g_pool + (size_t)batch[n] * 128 + c4;
    asm volatile("red.global.add.v4.f32 [%0], {%1,%2,%3,%4};"
                 :: "l"(p), "f"(v.x), "f"(v.y), "f"(v.z), "f"(v.w) : "memory");
}

__global__ void bcast_kernel(const int* __restrict__ batch) {
    int idx = blockIdx.x * blockDim.x + threadIdx.x;   // N*32 threads
    int n = idx >> 5;
    if (n >= NN) return;
    int c4 = (idx & 31) << 2;
    float4 v = *(const float4*)&g_pool[(size_t)batch[n] * 128 + c4];
    *(float4*)&g_HS[(size_t)n * HSW + 512 + c4] = v;
}

// ---------------------------------------------------------------------------
// Final: out[n] = sigmoid(Z1[n,:] . fW + fb)
// ---------------------------------------------------------------------------
__global__ void final_kernel(const float* __restrict__ Z,
                             const float* __restrict__ fW,
                             const float* __restrict__ fb,
                             float* __restrict__ out) {
    int idx = blockIdx.x * blockDim.x + threadIdx.x;
    int n = idx >> 5;
    if (n >= NN) return;
    int lane = idx & 31;
    float s = 0.f;
#pragma unroll
    for (int j = lane; j < CLSD; j += 32)
        s = fmaf(Z[(size_t)n * CLSD + j], fW[j], s);
#pragma unroll
    for (int o = 16; o; o >>= 1) s += __shfl_xor_sync(0xffffffffu, s, o);
    if (lane == 0) {
        float z = s + fb[0];
        out[n] = 1.f / (1.f + expf(-z));
    }
}

// ---------------------------------------------------------------------------
// Launch
// ---------------------------------------------------------------------------
extern "C" void kernel_launch(void* const* d_in, const int* in_sizes, int n_in,
                              void* d_out, int out_size) {
    const float* x    = (const float*)d_in[0];
    const int*   ei   = (const int*)d_in[1];
    const float* attr = (const float*)d_in[2];
    const int*   batch= (const int*)d_in[3];
    const float* c1W  = (const float*)d_in[4];
    const float* c1b  = (const float*)d_in[5];
    const float* c1g  = (const float*)d_in[6];
    const float* c1be = (const float*)d_in[7];
    const float* c1eW = (const float*)d_in[8];
    const float* c1eb = (const float*)d_in[9];
    const float* cW   = (const float*)d_in[10];
    const float* cb   = (const float*)d_in[11];
    const float* cg   = (const float*)d_in[12];
    const float* cbe  = (const float*)d_in[13];
    const float* ceW  = (const float*)d_in[14];
    const float* ceb  = (const float*)d_in[15];
    const float* k1W  = (const float*)d_in[16];
    const float* k1b  = (const float*)d_in[17];
    const float* kW   = (const float*)d_in[18];
    const float* kb   = (const float*)d_in[19];
    const float* fW   = (const float*)d_in[20];
    const float* fb   = (const float*)d_in[21];
    float* out = (float*)d_out;

    const int* srcp = ei;
    const int* dstp = ei + EE;

    const float bn_inv = (float)(1.0 / (double)((float)sqrt(1.0 + 1e-5)));

    float *agg, *h0, *HS, *z1, *z2;
    cudaGetSymbolAddress((void**)&agg, g_agg);
    cudaGetSymbolAddress((void**)&h0,  g_h0);
    cudaGetSymbolAddress((void**)&HS,  g_HS);
    cudaGetSymbolAddress((void**)&z1,  g_z1);
    cudaGetSymbolAddress((void**)&z2,  g_z2);

    // ---- CSR build (once per call) ----
    csr_zero_kernel<<<(NN + 255) / 256, 256>>>();
    csr_count_kernel<<<(EE + 255) / 256, 256>>>(dstp);
    csr_scan_kernel<<<1, 1024>>>();
    csr_fill_kernel<<<(EE + 255) / 256, 256>>>(dstp);

    const int GATHER_BLOCKS = (NN * 32 + 255) / 256;

    // ---- conv1 (64 -> 128) ----
    {
        gather_kernel<64><<<GATHER_BLOCKS, 256>>>(attr, srcp, x, INRR, c1eW, c1eb, agg);
        dim3 grid(1, (NN + 127) / 128);
        tf32_gemm<2><<<grid, 256>>>(agg, 64, c1W, c1b, c1g, c1be,
                                    h0, 128, NN, 64, 128, bn_inv);
    }

    // ---- conv loop (4 layers, 128 -> 128), outputs into HS cols i*128 ----
    for (int i = 0; i < 4; i++) {
        const float* inPtr = (i == 0) ? h0 : (HS + (size_t)(i - 1) * 128);
        int ldin = (i == 0) ? 128 : HSW;
        gather_kernel<128><<<GATHER_BLOCKS, 256>>>(attr, srcp, inPtr, ldin,
                                                   ceW + (size_t)i * EDD * OUTD,
                                                   ceb + (size_t)i * OUTD, agg);
        dim3 grid(1, (NN + 127) / 128);
        tf32_gemm<2><<<grid, 256>>>(agg, 128,
                                    cW + (size_t)i * OUTD * OUTD,
                                    cb + (size_t)i * OUTD,
                                    cg + (size_t)i * OUTD,
                                    cbe + (size_t)i * OUTD,
                                    HS + (size_t)i * 128, HSW,
                                    NN, 128, 128, bn_inv);
    }

    // ---- global_add_pool of final h (HS col 384) + broadcast into col 512 ----
    zero_pool_kernel<<<(NMOL * 128 / 4 + 255) / 256, 256>>>();
    pool_kernel<<<(NN * 32 + 255) / 256, 256>>>(batch);
    bcast_kernel<<<(NN * 32 + 255) / 256, 256>>>(batch);

    // ---- classifier ----
    {
        dim3 grid1(CLSD / 128, (NN + 127) / 128);
        tf32_gemm<0><<<grid1, 256>>>(HS, HSW, k1W, k1b, nullptr, nullptr,
                                     z1, CLSD, NN, HSW, CLSD, bn_inv);
        tf32_gemm<1><<<grid1, 256>>>(z1, CLSD, kW, kb, nullptr, nullptr,
                                     z2, CLSD, NN, CLSD, CLSD, bn_inv);
        tf32_gemm<1><<<grid1, 256>>>(z2, CLSD, kW + CLSD * CLSD, kb + CLSD,
                                     nullptr, nullptr,
                                     z1, CLSD, NN, CLSD, CLSD, bn_inv);
    }

    // ---- final dot + sigmoid ----
    final_kernel<<<(NN * 32 + 255) / 256, 256>>>(z1, fW, fb, out);
}

// round 3
// speedup vs baseline: 1.3738x; 1.0653x over previous
#include <cuda_runtime.h>
#include <cuda_bf16.h>
#include <math.h>

// Problem constants
#define NN   50000
#define EE   800000
#define NMOL 2000
#define INRR 64
#define OUTD 128
#define EDD  16
#define CLSD 256
#define HSW  640   // OUT*(L_CONV+1)

// Static scratch (no allocations allowed)
__device__ float g_agg[(size_t)NN * 128];
__device__ float g_h0[(size_t)NN * 128];
__device__ float g_HS[(size_t)NN * HSW];
__device__ float g_pool[(size_t)NMOL * 128];
__device__ float g_z1[(size_t)NN * CLSD];
__device__ float g_z2[(size_t)NN * CLSD];
// CSR (by dst)
__device__ int g_cnt[NN];
__device__ int g_off[NN + 1];
__device__ int g_cur[NN];
__device__ int g_eid[EE];

__device__ __forceinline__ float dleaky(float v) {
    float t = v > 0.f ? v : 0.01f * v;
    return t > 0.f ? t : 0.01f * t;
}
__device__ __forceinline__ float leaky1(float v) {
    return v > 0.f ? v : 0.01f * v;
}

// ---------------------------------------------------------------------------
// CSR build kernels
// ---------------------------------------------------------------------------
__global__ void csr_zero_kernel() {
    int i = blockIdx.x * blockDim.x + threadIdx.x;
    if (i < NN) g_cnt[i] = 0;
}
__global__ void csr_count_kernel(const int* __restrict__ dstv) {
    int e = blockIdx.x * blockDim.x + threadIdx.x;
    if (e < EE) atomicAdd(&g_cnt[dstv[e]], 1);
}
__global__ void csr_scan_kernel() {
    __shared__ int part[1024];
    const int CH = (NN + 1023) / 1024;
    int t = threadIdx.x;
    int start = t * CH;
    int sum = 0;
    for (int i = 0; i < CH; i++) {
        int idx = start + i;
        if (idx < NN) sum += g_cnt[idx];
    }
    part[t] = sum;
    __syncthreads();
    for (int o = 1; o < 1024; o <<= 1) {
        int v = (t >= o) ? part[t - o] : 0;
        __syncthreads();
        part[t] += v;
        __syncthreads();
    }
    int run = part[t] - sum;
    for (int i = 0; i < CH; i++) {
        int idx = start + i;
        if (idx < NN) {
            g_off[idx] = run;
            g_cur[idx] = run;
            run += g_cnt[idx];
        }
    }
    if (t == 0) g_off[NN] = EE;
}
__global__ void csr_fill_kernel(const int* __restrict__ dstv) {
    int e = blockIdx.x * blockDim.x + threadIdx.x;
    if (e < EE) {
        int pos = atomicAdd(&g_cur[dstv[e]], 1);
        g_eid[pos] = e;
    }
}

// ---------------------------------------------------------------------------
// Gather-based edge aggregation: warp per node, 1-deep software pipeline.
//   agg[n] = x[n] + sum_{e: dst=n} relu(x[src[e]] + attr[e]@eW + eb)
// ---------------------------------------------------------------------------
template <int D>
__global__ __launch_bounds__(128)
void gather_kernel(const float* __restrict__ attr,
                   const int* __restrict__ src,
                   const float* __restrict__ x, int ldx,
                   const float* __restrict__ eW,
                   const float* __restrict__ eb,
                   float* __restrict__ agg) {
    constexpr int C = D / 32;                 // cols per lane (2 or 4)
    const int lane = threadIdx.x & 31;
    int n = (blockIdx.x * blockDim.x + threadIdx.x) >> 5;
    if (n >= NN) return;

    float wreg[16 * C];
#pragma unroll
    for (int k = 0; k < 16; k++)
#pragma unroll
        for (int c = 0; c < C; c++)
            wreg[k * C + c] = eW[k * D + lane * C + c];
    float ebr[C];
#pragma unroll
    for (int c = 0; c < C; c++) ebr[c] = eb[lane * C + c];

    float acc[C];
    if (C == 4) {
        float4 xv = *(const float4*)&x[(size_t)n * ldx + lane * 4];
        acc[0] = xv.x; acc[1] = xv.y; acc[2] = xv.z; acc[3] = xv.w;
    } else {
        float2 xv = *(const float2*)&x[(size_t)n * ldx + lane * 2];
        acc[0] = xv.x; acc[1] = xv.y;
    }

    int i = g_off[n], s1 = g_off[n + 1];
    if (i < s1) {
        // prologue loads
        int eid = __ldg(&g_eid[i]);
        int s = __ldg(&src[eid]);
        float a = __ldg(&attr[(size_t)eid * 16 + (lane & 15)]);
        float xr[C];
        if (C == 4) {
            float4 xv = *(const float4*)&x[(size_t)s * ldx + lane * 4];
            xr[0] = xv.x; xr[1] = xv.y; xr[2] = xv.z; xr[3] = xv.w;
        } else {
            float2 xv = *(const float2*)&x[(size_t)s * ldx + lane * 2];
            xr[0] = xv.x; xr[1] = xv.y;
        }
        while (i < s1) {
            i++;
            // prefetch next edge
            float a2 = 0.f;
            float xr2[C];
#pragma unroll
            for (int c = 0; c < C; c++) xr2[c] = 0.f;
            if (i < s1) {
                int eid2 = __ldg(&g_eid[i]);
                int s2 = __ldg(&src[eid2]);
                a2 = __ldg(&attr[(size_t)eid2 * 16 + (lane & 15)]);
                if (C == 4) {
                    float4 xv = *(const float4*)&x[(size_t)s2 * ldx + lane * 4];
                    xr2[0] = xv.x; xr2[1] = xv.y; xr2[2] = xv.z; xr2[3] = xv.w;
                } else {
                    float2 xv = *(const float2*)&x[(size_t)s2 * ldx + lane * 2];
                    xr2[0] = xv.x; xr2[1] = xv.y;
                }
            }
            // MLP + relu + accumulate for current edge
            float ecc[C];
#pragma unroll
            for (int c = 0; c < C; c++) ecc[c] = ebr[c];
#pragma unroll
            for (int k = 0; k < 16; k++) {
                float av = __shfl_sync(0xffffffffu, a, k);
#pragma unroll
                for (int c = 0; c < C; c++) ecc[c] = fmaf(av, wreg[k * C + c], ecc[c]);
            }
#pragma unroll
            for (int c = 0; c < C; c++) {
                float m = xr[c] + ecc[c];
                acc[c] += m > 0.f ? m : 0.f;
            }
            a = a2;
#pragma unroll
            for (int c = 0; c < C; c++) xr[c] = xr2[c];
        }
    }
    if (C == 4) {
        *(float4*)&g_agg[(size_t)n * D + lane * 4] =
            make_float4(acc[0], acc[1], acc[2], acc[3]);
    } else {
        *(float2*)&g_agg[(size_t)n * D + lane * 2] = make_float2(acc[0], acc[1]);
    }
}

// ---------------------------------------------------------------------------
// Split-bf16 tensor-core GEMM: C = act(scale(A[N,K] @ B[K,M] + bias))
// A = Ah + Al (bf16 each); C ≈ Ah*Bh + Ah*Bl + Al*Bh (error ~2^-18).
// 128x128 tile, BK=16, 256 threads (8 warps 2x4), warp tile 64x32,
// mma.sync.m16n8k16.bf16, register-prefetch pipeline over k tiles.
//   ACT: 0 = none, 1 = leaky, 2 = double-leaky. BN applied if gamma != null.
// ---------------------------------------------------------------------------
__device__ __forceinline__ void mma_bf16(float* acc, const unsigned* a, const unsigned* b) {
    asm volatile(
        "mma.sync.aligned.m16n8k16.row.col.f32.bf16.bf16.f32 "
        "{%0,%1,%2,%3}, {%4,%5,%6,%7}, {%8,%9}, {%0,%1,%2,%3};"
        : "+f"(acc[0]), "+f"(acc[1]), "+f"(acc[2]), "+f"(acc[3])
        : "r"(a[0]), "r"(a[1]), "r"(a[2]), "r"(a[3]), "r"(b[0]), "r"(b[1]));
}

__device__ __forceinline__ unsigned pack_bf16(float lo, float hi) {
    __nv_bfloat162 h = __floats2bfloat162_rn(lo, hi);  // lo -> low half
    return *(unsigned*)&h;
}

template <int ACT>
__global__ __launch_bounds__(256)
void bf16_gemm(const float* __restrict__ A, int lda,
               const float* __restrict__ B,
               const float* __restrict__ bias,
               const float* __restrict__ gamma,
               const float* __restrict__ beta,
               float* __restrict__ Cmat, int ldc,
               int Nrows, int K, int M, float bn_inv) {
    // [m or n][kp] bf16x2 words, kp = k/2 (8 words per 16-k tile), pad 9
    __shared__ unsigned sAh[128][9];
    __shared__ unsigned sAl[128][9];
    __shared__ unsigned sBh[128][9];
    __shared__ unsigned sBl[128][9];

    const int tid = threadIdx.x;
    const int lane = tid & 31;
    const int wid = tid >> 5;
    const int wm = (wid & 1) * 64;
    const int wn = (wid >> 1) * 32;
    const int row0 = blockIdx.y * 128;
    const int col0 = blockIdx.x * 128;

    float acc[16][4];
#pragma unroll
    for (int i = 0; i < 16; i++)
#pragma unroll
        for (int j = 0; j < 4; j++) acc[i][j] = 0.f;

    // staging registers
    float4 ga[2];
    float2 gbe[2], gbo[2];

    // A load mapping: idx = j*256+tid; m = idx>>2; kk = (idx&3)*4
    // B load mapping: idx = j*256+tid; n2 = idx&63 (n=2*n2); kp = idx>>6
    auto load_tile = [&](int k0) {
#pragma unroll
        for (int j = 0; j < 2; j++) {
            int idx = j * 256 + tid;
            int m = idx >> 2, kk = (idx & 3) << 2;
            int r = row0 + m;
            ga[j] = make_float4(0.f, 0.f, 0.f, 0.f);
            if (r < Nrows) ga[j] = *(const float4*)&A[(size_t)r * lda + k0 + kk];
            int n = (idx & 63) << 1, kp = idx >> 6;
            gbe[j] = *(const float2*)&B[(size_t)(k0 + 2 * kp) * M + col0 + n];
            gbo[j] = *(const float2*)&B[(size_t)(k0 + 2 * kp + 1) * M + col0 + n];
        }
    };

    load_tile(0);

    for (int k0 = 0; k0 < K; k0 += 16) {
        __syncthreads();
        // convert + store to smem
#pragma unroll
        for (int j = 0; j < 2; j++) {
            int idx = j * 256 + tid;
            int m = idx >> 2, kp = (idx & 3) << 1;   // kp, kp+1
            float4 v = ga[j];
            float hx = __bfloat162float(__float2bfloat16(v.x));
            float hy = __bfloat162float(__float2bfloat16(v.y));
            float hz = __bfloat162float(__float2bfloat16(v.z));
            float hw = __bfloat162float(__float2bfloat16(v.w));
            sAh[m][kp]     = pack_bf16(hx, hy);
            sAh[m][kp + 1] = pack_bf16(hz, hw);
            sAl[m][kp]     = pack_bf16(v.x - hx, v.y - hy);
            sAl[m][kp + 1] = pack_bf16(v.z - hz, v.w - hw);

            int n = (idx & 63) << 1, bkp = idx >> 6;
            float2 e = gbe[j], o = gbo[j];
            float hex = __bfloat162float(__float2bfloat16(e.x));
            float hox = __bfloat162float(__float2bfloat16(o.x));
            float hey = __bfloat162float(__float2bfloat16(e.y));
            float hoy = __bfloat162float(__float2bfloat16(o.y));
            sBh[n][bkp]     = pack_bf16(hex, hox);
            sBl[n][bkp]     = pack_bf16(e.x - hex, o.x - hox);
            sBh[n + 1][bkp] = pack_bf16(hey, hoy);
            sBl[n + 1][bkp] = pack_bf16(e.y - hey, o.y - hoy);
        }
        __syncthreads();

        if (k0 + 16 < K) load_tile(k0 + 16);   // prefetch next tile

        // fragments
        unsigned af[4][4], bh[4][2], bl[4][2];
        const int ar = lane >> 2, ak = lane & 3;
#pragma unroll
        for (int i = 0; i < 4; i++) {
            int m = wm + i * 16 + ar;
            af[i][0] = sAh[m][ak];
            af[i][1] = sAh[m + 8][ak];
            af[i][2] = sAh[m][ak + 4];
            af[i][3] = sAh[m + 8][ak + 4];
        }
#pragma unroll
        for (int j = 0; j < 4; j++) {
            int nn = wn + j * 8 + (lane >> 2);
            bh[j][0] = sBh[nn][lane & 3];
            bh[j][1] = sBh[nn][(lane & 3) + 4];
            bl[j][0] = sBl[nn][lane & 3];
            bl[j][1] = sBl[nn][(lane & 3) + 4];
        }
#pragma unroll
        for (int i = 0; i < 4; i++)
#pragma unroll
            for (int j = 0; j < 4; j++) mma_bf16(acc[i * 4 + j], af[i], bh[j]);
#pragma unroll
        for (int i = 0; i < 4; i++)
#pragma unroll
            for (int j = 0; j < 4; j++) mma_bf16(acc[i * 4 + j], af[i], bl[j]);
        // reload A with lo parts
#pragma unroll
        for (int i = 0; i < 4; i++) {
            int m = wm + i * 16 + ar;
            af[i][0] = sAl[m][ak];
            af[i][1] = sAl[m + 8][ak];
            af[i][2] = sAl[m][ak + 4];
            af[i][3] = sAl[m + 8][ak + 4];
        }
#pragma unroll
        for (int i = 0; i < 4; i++)
#pragma unroll
            for (int j = 0; j < 4; j++) mma_bf16(acc[i * 4 + j], af[i], bh[j]);
    }

    // epilogue
#pragma unroll
    for (int i = 0; i < 4; i++) {
#pragma unroll
        for (int j = 0; j < 4; j++) {
            int r = row0 + wm + i * 16 + (lane >> 2);
            int c = col0 + wn + j * 8 + (lane & 3) * 2;
            float* ap = acc[i * 4 + j];
#pragma unroll
            for (int h = 0; h < 2; h++) {
                int rr = r + h * 8;
                if (rr >= Nrows) continue;
                float v0 = ap[h * 2 + 0] + bias[c];
                float v1 = ap[h * 2 + 1] + bias[c + 1];
                if (gamma != nullptr) {
                    v0 = gamma[c] * (v0 * bn_inv) + beta[c];
                    v1 = gamma[c + 1] * (v1 * bn_inv) + beta[c + 1];
                }
                if (ACT == 1) { v0 = leaky1(v0); v1 = leaky1(v1); }
                else if (ACT == 2) { v0 = dleaky(v0); v1 = dleaky(v1); }
                *(float2*)&Cmat[(size_t)rr * ldc + c] = make_float2(v0, v1);
            }
        }
    }
}

// ---------------------------------------------------------------------------
// Pooling: zero, accumulate (red.v4), broadcast back into HS cols 512:640
// ---------------------------------------------------------------------------
__global__ void zero_pool_kernel() {
    int idx = blockIdx.x * blockDim.x + threadIdx.x;
    if (idx < NMOL * 128 / 4)
        *(float4*)&g_pool[idx * 4] = make_float4(0.f, 0.f, 0.f, 0.f);
}

__global__ void pool_kernel(const int* __restrict__ batch) {
    int idx = blockIdx.x * blockDim.x + threadIdx.x;
    int n = idx >> 5;
    if (n >= NN) return;
    int c4 = (idx & 31) << 2;
    float4 v = *(const float4*)&g_HS[(size_t)n * HSW + 384 + c4];
    float* p = g_pool + (size_t)batch[n] * 128 + c4;
    asm volatile("red.global.add.v4.f32 [%0], {%1,%2,%3,%4};"
                 :: "l"(p), "f"(v.x), "f"(v.y), "f"(v.z), "f"(v.w) : "memory");
}

__global__ void bcast_kernel(const int* __restrict__ batch) {
    int idx = blockIdx.x * blockDim.x + threadIdx.x;
    int n = idx >> 5;
    if (n >= NN) return;
    int c4 = (idx & 31) << 2;
    float4 v = *(const float4*)&g_pool[(size_t)batch[n] * 128 + c4];
    *(float4*)&g_HS[(size_t)n * HSW + 512 + c4] = v;
}

// ---------------------------------------------------------------------------
// Final: out[n] = sigmoid(Z1[n,:] . fW + fb)
// ---------------------------------------------------------------------------
__global__ void final_kernel(const float* __restrict__ Z,
                             const float* __restrict__ fW,
                             const float* __restrict__ fb,
                             float* __restrict__ out) {
    int idx = blockIdx.x * blockDim.x + threadIdx.x;
    int n = idx >> 5;
    if (n >= NN) return;
    int lane = idx & 31;
    float s = 0.f;
#pragma unroll
    for (int j = lane; j < CLSD; j += 32)
        s = fmaf(Z[(size_t)n * CLSD + j], fW[j], s);
#pragma unroll
    for (int o = 16; o; o >>= 1) s += __shfl_xor_sync(0xffffffffu, s, o);
    if (lane == 0) {
        float z = s + fb[0];
        out[n] = 1.f / (1.f + expf(-z));
    }
}

// ---------------------------------------------------------------------------
// Launch
// ---------------------------------------------------------------------------
extern "C" void kernel_launch(void* const* d_in, const int* in_sizes, int n_in,
                              void* d_out, int out_size) {
    const float* x    = (const float*)d_in[0];
    const int*   ei   = (const int*)d_in[1];
    const float* attr = (const float*)d_in[2];
    const int*   batch= (const int*)d_in[3];
    const float* c1W  = (const float*)d_in[4];
    const float* c1b  = (const float*)d_in[5];
    const float* c1g  = (const float*)d_in[6];
    const float* c1be = (const float*)d_in[7];
    const float* c1eW = (const float*)d_in[8];
    const float* c1eb = (const float*)d_in[9];
    const float* cW   = (const float*)d_in[10];
    const float* cb   = (const float*)d_in[11];
    const float* cg   = (const float*)d_in[12];
    const float* cbe  = (const float*)d_in[13];
    const float* ceW  = (const float*)d_in[14];
    const float* ceb  = (const float*)d_in[15];
    const float* k1W  = (const float*)d_in[16];
    const float* k1b  = (const float*)d_in[17];
    const float* kW   = (const float*)d_in[18];
    const float* kb   = (const float*)d_in[19];
    const float* fW   = (const float*)d_in[20];
    const float* fb   = (const float*)d_in[21];
    float* out = (float*)d_out;

    const int* srcp = ei;
    const int* dstp = ei + EE;

    const float bn_inv = (float)(1.0 / (double)((float)sqrt(1.0 + 1e-5)));

    float *agg, *h0, *HS, *z1, *z2;
    cudaGetSymbolAddress((void**)&agg, g_agg);
    cudaGetSymbolAddress((void**)&h0,  g_h0);
    cudaGetSymbolAddress((void**)&HS,  g_HS);
    cudaGetSymbolAddress((void**)&z1,  g_z1);
    cudaGetSymbolAddress((void**)&z2,  g_z2);

    // ---- CSR build (once per call) ----
    csr_zero_kernel<<<(NN + 255) / 256, 256>>>();
    csr_count_kernel<<<(EE + 255) / 256, 256>>>(dstp);
    csr_scan_kernel<<<1, 1024>>>();
    csr_fill_kernel<<<(EE + 255) / 256, 256>>>(dstp);

    const int GATHER_BLOCKS = (NN * 32 + 127) / 128;

    // ---- conv1 (64 -> 128) ----
    {
        gather_kernel<64><<<GATHER_BLOCKS, 128>>>(attr, srcp, x, INRR, c1eW, c1eb, agg);
        dim3 grid(1, (NN + 127) / 128);
        bf16_gemm<2><<<grid, 256>>>(agg, 64, c1W, c1b, c1g, c1be,
                                    h0, 128, NN, 64, 128, bn_inv);
    }

    // ---- conv loop (4 layers, 128 -> 128), outputs into HS cols i*128 ----
    for (int i = 0; i < 4; i++) {
        const float* inPtr = (i == 0) ? h0 : (HS + (size_t)(i - 1) * 128);
        int ldin = (i == 0) ? 128 : HSW;
        gather_kernel<128><<<GATHER_BLOCKS, 128>>>(attr, srcp, inPtr, ldin,
                                                   ceW + (size_t)i * EDD * OUTD,
                                                   ceb + (size_t)i * OUTD, agg);
        dim3 grid(1, (NN + 127) / 128);
        bf16_gemm<2><<<grid, 256>>>(agg, 128,
                                    cW + (size_t)i * OUTD * OUTD,
                                    cb + (size_t)i * OUTD,
                                    cg + (size_t)i * OUTD,
                                    cbe + (size_t)i * OUTD,
                                    HS + (size_t)i * 128, HSW,
                                    NN, 128, 128, bn_inv);
    }

    // ---- global_add_pool of final h (HS col 384) + broadcast into col 512 ----
    zero_pool_kernel<<<(NMOL * 128 / 4 + 255) / 256, 256>>>();
    pool_kernel<<<(NN * 32 + 255) / 256, 256>>>(batch);
    bcast_kernel<<<(NN * 32 + 255) / 256, 256>>>(batch);

    // ---- classifier ----
    {
        dim3 grid1(CLSD / 128, (NN + 127) / 128);
        bf16_gemm<0><<<grid1, 256>>>(HS, HSW, k1W, k1b, nullptr, nullptr,
                                     z1, CLSD, NN, HSW, CLSD, bn_inv);
        bf16_gemm<1><<<grid1, 256>>>(z1, CLSD, kW, kb, nullptr, nullptr,
                                     z2, CLSD, NN, CLSD, CLSD, bn_inv);
        bf16_gemm<1><<<grid1, 256>>>(z2, CLSD, kW + CLSD * CLSD, kb + CLSD,
                                     nullptr, nullptr,
                                     z1, CLSD, NN, CLSD, CLSD, bn_inv);
    }

    // ---- final dot + sigmoid ----
    final_kernel<<<(NN * 32 + 255) / 256, 256>>>(z1, fW, fb, out);
}

// round 4
// speedup vs baseline: 1.9538x; 1.4221x over previous
#include <cuda_runtime.h>
#include <cuda_bf16.h>
#include <math.h>

// Problem constants
#define NN   50000
#define EE   800000
#define NMOL 2000
#define INRR 64
#define OUTD 128
#define EDD  16
#define CLSD 256
#define HSW  640   // OUT*(L_CONV+1)

// Static scratch (no allocations allowed)
__device__ float g_agg[(size_t)NN * 128];
__device__ float g_h0[(size_t)NN * 128];
__device__ float g_HS[(size_t)NN * HSW];
__device__ float g_pool[(size_t)NMOL * 128];
__device__ float g_z1[(size_t)NN * CLSD];
__device__ float g_z2[(size_t)NN * CLSD];
// CSR (by dst)
__device__ int g_cnt[NN];
__device__ int g_off[NN + 1];
__device__ int g_cur[NN];
__device__ int g_eid[EE];
__device__ int g_srcs[EE];                       // CSR-ordered src node
__device__ float g_attrs[(size_t)EE * 16];       // CSR-ordered edge_attr

__device__ __forceinline__ float dleaky(float v) {
    float t = v > 0.f ? v : 0.01f * v;
    return t > 0.f ? t : 0.01f * t;
}
__device__ __forceinline__ float leaky1(float v) {
    return v > 0.f ? v : 0.01f * v;
}

// ---------------------------------------------------------------------------
// CSR build kernels
// ---------------------------------------------------------------------------
__global__ void csr_zero_kernel() {
    int i = blockIdx.x * blockDim.x + threadIdx.x;
    if (i < NN) g_cnt[i] = 0;
}
__global__ void csr_count_kernel(const int* __restrict__ dstv) {
    int e = blockIdx.x * blockDim.x + threadIdx.x;
    if (e < EE) atomicAdd(&g_cnt[dstv[e]], 1);
}
__global__ void csr_scan_kernel() {
    __shared__ int part[1024];
    const int CH = (NN + 1023) / 1024;
    int t = threadIdx.x;
    int start = t * CH;
    int sum = 0;
    for (int i = 0; i < CH; i++) {
        int idx = start + i;
        if (idx < NN) sum += g_cnt[idx];
    }
    part[t] = sum;
    __syncthreads();
    for (int o = 1; o < 1024; o <<= 1) {
        int v = (t >= o) ? part[t - o] : 0;
        __syncthreads();
        part[t] += v;
        __syncthreads();
    }
    int run = part[t] - sum;
    for (int i = 0; i < CH; i++) {
        int idx = start + i;
        if (idx < NN) {
            g_off[idx] = run;
            g_cur[idx] = run;
            run += g_cnt[idx];
        }
    }
    if (t == 0) g_off[NN] = EE;
}
__global__ void csr_fill_kernel(const int* __restrict__ dstv) {
    int e = blockIdx.x * blockDim.x + threadIdx.x;
    if (e < EE) {
        int pos = atomicAdd(&g_cur[dstv[e]], 1);
        g_eid[pos] = e;
    }
}
// Permute edge payload into CSR order: g_attrs[pos] = attr[eid], g_srcs[pos] = src[eid]
__global__ void csr_permute_kernel(const float* __restrict__ attr,
                                   const int* __restrict__ src) {
    int idx = blockIdx.x * blockDim.x + threadIdx.x;   // EE*16 threads
    if (idx >= EE * 16) return;
    int pos = idx >> 4, c = idx & 15;
    int e = g_eid[pos];
    g_attrs[idx] = __ldg(&attr[(size_t)e * 16 + c]);
    if (c == 0) g_srcs[pos] = __ldg(&src[e]);
}

// ---------------------------------------------------------------------------
// Gather-based edge aggregation: warp per node.
//   agg[n] = x[n] + sum_{e: dst=n} relu(x[src[e]] + attr[e]@eW + eb)
// srcs/attrs are CSR-ordered (sequential reads); only x[src] is random.
// 2-wide, double-buffered software pipeline.
// ---------------------------------------------------------------------------
template <int D>
__global__ __launch_bounds__(128)
void gather_kernel(const float* __restrict__ x, int ldx,
                   const float* __restrict__ eW,
                   const float* __restrict__ eb,
                   float* __restrict__ agg) {
    constexpr int C = D / 32;                 // cols per lane (2 or 4)
    const int lane = threadIdx.x & 31;
    int n = (blockIdx.x * blockDim.x + threadIdx.x) >> 5;
    if (n >= NN) return;

    float wreg[16 * C];
#pragma unroll
    for (int k = 0; k < 16; k++)
#pragma unroll
        for (int c = 0; c < C; c++)
            wreg[k * C + c] = eW[k * D + lane * C + c];
    float ebr[C];
#pragma unroll
    for (int c = 0; c < C; c++) ebr[c] = eb[lane * C + c];

    float acc[C];
    if constexpr (C == 4) {
        float4 xv = *(const float4*)&x[(size_t)n * ldx + lane * 4];
        acc[0] = xv.x; acc[1] = xv.y; acc[2] = xv.z; acc[3] = xv.w;
    } else {
        float2 xv = *(const float2*)&x[(size_t)n * ldx + lane * 2];
        acc[0] = xv.x; acc[1] = xv.y;
    }

    const int i1 = g_off[n + 1];
    int i0 = g_off[n];

    // current pair
    float a0 = 0.f, a1 = 0.f;
    float xr0[C], xr1[C];
    // next pair
    float na0, na1;
    float nxr0[C], nxr1[C];

    auto ld_edge = [&](int pos, float& a, float (&xr)[C]) {
        if (pos < i1) {
            int s = __ldg(&g_srcs[pos]);
            a = __ldg(&g_attrs[(size_t)pos * 16 + (lane & 15)]);
            if constexpr (C == 4) {
                float4 v = *(const float4*)&x[(size_t)s * ldx + lane * 4];
                xr[0] = v.x; xr[1] = v.y; xr[2] = v.z; xr[3] = v.w;
            } else {
                float2 v = *(const float2*)&x[(size_t)s * ldx + lane * 2];
                xr[0] = v.x; xr[1] = v.y;
            }
        }
    };

    if (i0 < i1) {
        ld_edge(i0, a0, xr0);
        ld_edge(i0 + 1, a1, xr1);
        for (int base = i0; base < i1; base += 2) {
            // prefetch next pair
            ld_edge(base + 2, na0, nxr0);
            ld_edge(base + 3, na1, nxr1);
            // compute both MLPs interleaved
            float e0[C], e1[C];
#pragma unroll
            for (int c = 0; c < C; c++) { e0[c] = ebr[c]; e1[c] = ebr[c]; }
#pragma unroll
            for (int k = 0; k < 16; k++) {
                float av0 = __shfl_sync(0xffffffffu, a0, k);
                float av1 = __shfl_sync(0xffffffffu, a1, k);
#pragma unroll
                for (int c = 0; c < C; c++) {
                    e0[c] = fmaf(av0, wreg[k * C + c], e0[c]);
                    e1[c] = fmaf(av1, wreg[k * C + c], e1[c]);
                }
            }
#pragma unroll
            for (int c = 0; c < C; c++) {
                float m = xr0[c] + e0[c];
                acc[c] += m > 0.f ? m : 0.f;
            }
            if (base + 1 < i1) {
#pragma unroll
                for (int c = 0; c < C; c++) {
                    float m = xr1[c] + e1[c];
                    acc[c] += m > 0.f ? m : 0.f;
                }
            }
            // rotate buffers
            a0 = na0; a1 = na1;
#pragma unroll
            for (int c = 0; c < C; c++) { xr0[c] = nxr0[c]; xr1[c] = nxr1[c]; }
        }
    }

    if constexpr (C == 4) {
        *(float4*)&g_agg[(size_t)n * D + lane * 4] =
            make_float4(acc[0], acc[1], acc[2], acc[3]);
    } else {
        *(float2*)&g_agg[(size_t)n * D + lane * 2] = make_float2(acc[0], acc[1]);
    }
}

// ---------------------------------------------------------------------------
// Split-bf16 tensor-core GEMM: C = act(scale(A[N,K] @ B[K,M] + bias))
// A = Ah + Al (bf16 each); C ≈ Ah*Bh + Ah*Bl + Al*Bh (error ~2^-18).
// 128x128 tile, BK=16, 256 threads (8 warps 2x4), warp tile 64x32,
// mma.sync.m16n8k16.bf16, register-prefetch pipeline over k tiles.
// ---------------------------------------------------------------------------
__device__ __forceinline__ void mma_bf16(float* acc, const unsigned* a, const unsigned* b) {
    asm volatile(
        "mma.sync.aligned.m16n8k16.row.col.f32.bf16.bf16.f32 "
        "{%0,%1,%2,%3}, {%4,%5,%6,%7}, {%8,%9}, {%0,%1,%2,%3};"
        : "+f"(acc[0]), "+f"(acc[1]), "+f"(acc[2]), "+f"(acc[3])
        : "r"(a[0]), "r"(a[1]), "r"(a[2]), "r"(a[3]), "r"(b[0]), "r"(b[1]));
}

__device__ __forceinline__ unsigned pack_bf16(float lo, float hi) {
    __nv_bfloat162 h = __floats2bfloat162_rn(lo, hi);
    return *(unsigned*)&h;
}

template <int ACT>
__global__ __launch_bounds__(256)
void bf16_gemm(const float* __restrict__ A, int lda,
               const float* __restrict__ B,
               const float* __restrict__ bias,
               const float* __restrict__ gamma,
               const float* __restrict__ beta,
               float* __restrict__ Cmat, int ldc,
               int Nrows, int K, int M, float bn_inv) {
    __shared__ unsigned sAh[128][9];
    __shared__ unsigned sAl[128][9];
    __shared__ unsigned sBh[128][9];
    __shared__ unsigned sBl[128][9];

    const int tid = threadIdx.x;
    const int lane = tid & 31;
    const int wid = tid >> 5;
    const int wm = (wid & 1) * 64;
    const int wn = (wid >> 1) * 32;
    const int row0 = blockIdx.y * 128;
    const int col0 = blockIdx.x * 128;

    float acc[16][4];
#pragma unroll
    for (int i = 0; i < 16; i++)
#pragma unroll
        for (int j = 0; j < 4; j++) acc[i][j] = 0.f;

    float4 ga[2];
    float2 gbe[2], gbo[2];

    auto load_tile = [&](int k0) {
#pragma unroll
        for (int j = 0; j < 2; j++) {
            int idx = j * 256 + tid;
            int m = idx >> 2, kk = (idx & 3) << 2;
            int r = row0 + m;
            ga[j] = make_float4(0.f, 0.f, 0.f, 0.f);
            if (r < Nrows) ga[j] = *(const float4*)&A[(size_t)r * lda + k0 + kk];
            int n = (idx & 63) << 1, kp = idx >> 6;
            gbe[j] = *(const float2*)&B[(size_t)(k0 + 2 * kp) * M + col0 + n];
            gbo[j] = *(const float2*)&B[(size_t)(k0 + 2 * kp + 1) * M + col0 + n];
        }
    };

    load_tile(0);

    for (int k0 = 0; k0 < K; k0 += 16) {
        __syncthreads();
#pragma unroll
        for (int j = 0; j < 2; j++) {
            int idx = j * 256 + tid;
            int m = idx >> 2, kp = (idx & 3) << 1;
            float4 v = ga[j];
            float hx = __bfloat162float(__float2bfloat16(v.x));
            float hy = __bfloat162float(__float2bfloat16(v.y));
            float hz = __bfloat162float(__float2bfloat16(v.z));
            float hw = __bfloat162float(__float2bfloat16(v.w));
            sAh[m][kp]     = pack_bf16(hx, hy);
            sAh[m][kp + 1] = pack_bf16(hz, hw);
            sAl[m][kp]     = pack_bf16(v.x - hx, v.y - hy);
            sAl[m][kp + 1] = pack_bf16(v.z - hz, v.w - hw);

            int n = (idx & 63) << 1, bkp = idx >> 6;
            float2 e = gbe[j], o = gbo[j];
            float hex = __bfloat162float(__float2bfloat16(e.x));
            float hox = __bfloat162float(__float2bfloat16(o.x));
            float hey = __bfloat162float(__float2bfloat16(e.y));
            float hoy = __bfloat162float(__float2bfloat16(o.y));
            sBh[n][bkp]     = pack_bf16(hex, hox);
            sBl[n][bkp]     = pack_bf16(e.x - hex, o.x - hox);
            sBh[n + 1][bkp] = pack_bf16(hey, hoy);
            sBl[n + 1][bkp] = pack_bf16(e.y - hey, o.y - hoy);
        }
        __syncthreads();

        if (k0 + 16 < K) load_tile(k0 + 16);

        unsigned af[4][4], bh[4][2], bl[4][2];
        const int ar = lane >> 2, ak = lane & 3;
#pragma unroll
        for (int i = 0; i < 4; i++) {
            int m = wm + i * 16 + ar;
            af[i][0] = sAh[m][ak];
            af[i][1] = sAh[m + 8][ak];
            af[i][2] = sAh[m][ak + 4];
            af[i][3] = sAh[m + 8][ak + 4];
        }
#pragma unroll
        for (int j = 0; j < 4; j++) {
            int nn = wn + j * 8 + (lane >> 2);
            bh[j][0] = sBh[nn][lane & 3];
            bh[j][1] = sBh[nn][(lane & 3) + 4];
            bl[j][0] = sBl[nn][lane & 3];
            bl[j][1] = sBl[nn][(lane & 3) + 4];
        }
#pragma unroll
        for (int i = 0; i < 4; i++)
#pragma unroll
            for (int j = 0; j < 4; j++) mma_bf16(acc[i * 4 + j], af[i], bh[j]);
#pragma unroll
        for (int i = 0; i < 4; i++)
#pragma unroll
            for (int j = 0; j < 4; j++) mma_bf16(acc[i * 4 + j], af[i], bl[j]);
#pragma unroll
        for (int i = 0; i < 4; i++) {
            int m = wm + i * 16 + ar;
            af[i][0] = sAl[m][ak];
            af[i][1] = sAl[m + 8][ak];
            af[i][2] = sAl[m][ak + 4];
            af[i][3] = sAl[m + 8][ak + 4];
        }
#pragma unroll
        for (int i = 0; i < 4; i++)
#pragma unroll
            for (int j = 0; j < 4; j++) mma_bf16(acc[i * 4 + j], af[i], bh[j]);
    }

    // epilogue
#pragma unroll
    for (int i = 0; i < 4; i++) {
#pragma unroll
        for (int j = 0; j < 4; j++) {
            int r = row0 + wm + i * 16 + (lane >> 2);
            int c = col0 + wn + j * 8 + (lane & 3) * 2;
            float* ap = acc[i * 4 + j];
#pragma unroll
            for (int h = 0; h < 2; h++) {
                int rr = r + h * 8;
                if (rr >= Nrows) continue;
                float v0 = ap[h * 2 + 0] + bias[c];
                float v1 = ap[h * 2 + 1] + bias[c + 1];
                if (gamma != nullptr) {
                    v0 = gamma[c] * (v0 * bn_inv) + beta[c];
                    v1 = gamma[c + 1] * (v1 * bn_inv) + beta[c + 1];
                }
                if (ACT == 1) { v0 = leaky1(v0); v1 = leaky1(v1); }
                else if (ACT == 2) { v0 = dleaky(v0); v1 = dleaky(v1); }
                *(float2*)&Cmat[(size_t)rr * ldc + c] = make_float2(v0, v1);
            }
        }
    }
}

// ---------------------------------------------------------------------------
// Pooling
// ---------------------------------------------------------------------------
__global__ void zero_pool_kernel() {
    int idx = blockIdx.x * blockDim.x + threadIdx.x;
    if (idx < NMOL * 128 / 4)
        *(float4*)&g_pool[idx * 4] = make_float4(0.f, 0.f, 0.f, 0.f);
}

__global__ void pool_kernel(const int* __restrict__ batch) {
    int idx = blockIdx.x * blockDim.x + threadIdx.x;
    int n = idx >> 5;
    if (n >= NN) return;
    int c4 = (idx & 31) << 2;
    float4 v = *(const float4*)&g_HS[(size_t)n * HSW + 384 + c4];
    float* p = g_pool + (size_t)batch[n] * 128 + c4;
    asm volatile("red.global.add.v4.f32 [%0], {%1,%2,%3,%4};"
                 :: "l"(p), "f"(v.x), "f"(v.y), "f"(v.z), "f"(v.w) : "memory");
}

__global__ void bcast_kernel(const int* __restrict__ batch) {
    int idx = blockIdx.x * blockDim.x + threadIdx.x;
    int n = idx >> 5;
    if (n >= NN) return;
    int c4 = (idx & 31) << 2;
    float4 v = *(const float4*)&g_pool[(size_t)batch[n] * 128 + c4];
    *(float4*)&g_HS[(size_t)n * HSW + 512 + c4] = v;
}

// ---------------------------------------------------------------------------
// Final: out[n] = sigmoid(Z1[n,:] . fW + fb)
// ---------------------------------------------------------------------------
__global__ void final_kernel(const float* __restrict__ Z,
                             const float* __restrict__ fW,
                             const float* __restrict__ fb,
                             float* __restrict__ out) {
    int idx = blockIdx.x * blockDim.x + threadIdx.x;
    int n = idx >> 5;
    if (n >= NN) return;
    int lane = idx & 31;
    float s = 0.f;
#pragma unroll
    for (int j = lane; j < CLSD; j += 32)
        s = fmaf(Z[(size_t)n * CLSD + j], fW[j], s);
#pragma unroll
    for (int o = 16; o; o >>= 1) s += __shfl_xor_sync(0xffffffffu, s, o);
    if (lane == 0) {
        float z = s + fb[0];
        out[n] = 1.f / (1.f + expf(-z));
    }
}

// ---------------------------------------------------------------------------
// Launch
// ---------------------------------------------------------------------------
extern "C" void kernel_launch(void* const* d_in, const int* in_sizes, int n_in,
                              void* d_out, int out_size) {
    const float* x    = (const float*)d_in[0];
    const int*   ei   = (const int*)d_in[1];
    const float* attr = (const float*)d_in[2];
    const int*   batch= (const int*)d_in[3];
    const float* c1W  = (const float*)d_in[4];
    const float* c1b  = (const float*)d_in[5];
    const float* c1g  = (const float*)d_in[6];
    const float* c1be = (const float*)d_in[7];
    const float* c1eW = (const float*)d_in[8];
    const float* c1eb = (const float*)d_in[9];
    const float* cW   = (const float*)d_in[10];
    const float* cb   = (const float*)d_in[11];
    const float* cg   = (const float*)d_in[12];
    const float* cbe  = (const float*)d_in[13];
    const float* ceW  = (const float*)d_in[14];
    const float* ceb  = (const float*)d_in[15];
    const float* k1W  = (const float*)d_in[16];
    const float* k1b  = (const float*)d_in[17];
    const float* kW   = (const float*)d_in[18];
    const float* kb   = (const float*)d_in[19];
    const float* fW   = (const float*)d_in[20];
    const float* fb   = (const float*)d_in[21];
    float* out = (float*)d_out;

    const int* srcp = ei;
    const int* dstp = ei + EE;

    const float bn_inv = (float)(1.0 / (double)((float)sqrt(1.0 + 1e-5)));

    float *agg, *h0, *HS, *z1, *z2;
    cudaGetSymbolAddress((void**)&agg, g_agg);
    cudaGetSymbolAddress((void**)&h0,  g_h0);
    cudaGetSymbolAddress((void**)&HS,  g_HS);
    cudaGetSymbolAddress((void**)&z1,  g_z1);
    cudaGetSymbolAddress((void**)&z2,  g_z2);

    // ---- CSR build + payload permute (once per call) ----
    csr_zero_kernel<<<(NN + 255) / 256, 256>>>();
    csr_count_kernel<<<(EE + 255) / 256, 256>>>(dstp);
    csr_scan_kernel<<<1, 1024>>>();
    csr_fill_kernel<<<(EE + 255) / 256, 256>>>(dstp);
    csr_permute_kernel<<<(EE * 16 + 255) / 256, 256>>>(attr, srcp);

    const int GATHER_BLOCKS = (NN * 32 + 127) / 128;

    // ---- conv1 (64 -> 128) ----
    {
        gather_kernel<64><<<GATHER_BLOCKS, 128>>>(x, INRR, c1eW, c1eb, agg);
        dim3 grid(1, (NN + 127) / 128);
        bf16_gemm<2><<<grid, 256>>>(agg, 64, c1W, c1b, c1g, c1be,
                                    h0, 128, NN, 64, 128, bn_inv);
    }

    // ---- conv loop (4 layers, 128 -> 128), outputs into HS cols i*128 ----
    for (int i = 0; i < 4; i++) {
        const float* inPtr = (i == 0) ? h0 : (HS + (size_t)(i - 1) * 128);
        int ldin = (i == 0) ? 128 : HSW;
        gather_kernel<128><<<GATHER_BLOCKS, 128>>>(inPtr, ldin,
                                                   ceW + (size_t)i * EDD * OUTD,
                                                   ceb + (size_t)i * OUTD, agg);
        dim3 grid(1, (NN + 127) / 128);
        bf16_gemm<2><<<grid, 256>>>(agg, 128,
                                    cW + (size_t)i * OUTD * OUTD,
                                    cb + (size_t)i * OUTD,
                                    cg + (size_t)i * OUTD,
                                    cbe + (size_t)i * OUTD,
                                    HS + (size_t)i * 128, HSW,
                                    NN, 128, 128, bn_inv);
    }

    // ---- global_add_pool + broadcast ----
    zero_pool_kernel<<<(NMOL * 128 / 4 + 255) / 256, 256>>>();
    pool_kernel<<<(NN * 32 + 255) / 256, 256>>>(batch);
    bcast_kernel<<<(NN * 32 + 255) / 256, 256>>>(batch);

    // ---- classifier ----
    {
        dim3 grid1(CLSD / 128, (NN + 127) / 128);
        bf16_gemm<0><<<grid1, 256>>>(HS, HSW, k1W, k1b, nullptr, nullptr,
                                     z1, CLSD, NN, HSW, CLSD, bn_inv);
        bf16_gemm<1><<<grid1, 256>>>(z1, CLSD, kW, kb, nullptr, nullptr,
                                     z2, CLSD, NN, CLSD, CLSD, bn_inv);
        bf16_gemm<1><<<grid1, 256>>>(z2, CLSD, kW + CLSD * CLSD, kb + CLSD,
                                     nullptr, nullptr,
                                     z1, CLSD, NN, CLSD, CLSD, bn_inv);
    }

    // ---- final dot + sigmoid ----
    final_kernel<<<(NN * 32 + 255) / 256, 256>>>(z1, fW, fb, out);
}

// round 5
// speedup vs baseline: 2.0191x; 1.0334x over previous
#include <cuda_runtime.h>
#include <cuda_bf16.h>
#include <math.h>

// Problem constants
#define NN   50000
#define EE   800000
#define NMOL 2000
#define INRR 64
#define OUTD 128
#define EDD  16
#define CLSD 256
#define HSW  640   // OUT*(L_CONV+1)

// Static scratch (no allocations allowed)
__device__ float g_agg[(size_t)NN * 128];
__device__ float g_h0[(size_t)NN * 128];
__device__ float g_HS[(size_t)NN * HSW];
__device__ float g_pool[(size_t)NMOL * 128];
__device__ float g_z1[(size_t)NN * CLSD];
__device__ float g_z2[(size_t)NN * CLSD];
// CSR (by dst)
__device__ int g_cnt[NN];
__device__ int g_off[NN + 1];
__device__ int g_cur[NN];
__device__ int g_eid[EE];
__device__ int g_srcs[EE];                       // CSR-ordered src node
__device__ float g_attrs[(size_t)EE * 16];       // CSR-ordered edge_attr

__device__ __forceinline__ float dleaky(float v) {
    float t = v > 0.f ? v : 0.01f * v;
    return t > 0.f ? t : 0.01f * t;
}
__device__ __forceinline__ float leaky1(float v) {
    return v > 0.f ? v : 0.01f * v;
}

// f32x2 helpers
__device__ __forceinline__ unsigned long long packf2(float lo, float hi) {
    unsigned long long r;
    asm("mov.b64 %0, {%1, %2};" : "=l"(r) : "r"(__float_as_uint(lo)), "r"(__float_as_uint(hi)));
    return r;
}
__device__ __forceinline__ unsigned long long dupf2(float v) {
    unsigned long long r;
    unsigned b = __float_as_uint(v);
    asm("mov.b64 %0, {%1, %1};" : "=l"(r) : "r"(b));
    return r;
}
__device__ __forceinline__ void fma2(unsigned long long& d,
                                     unsigned long long a, unsigned long long b) {
    asm("fma.rn.f32x2 %0, %1, %2, %0;" : "+l"(d) : "l"(a), "l"(b));
}
__device__ __forceinline__ void unpackf2(unsigned long long v, float& lo, float& hi) {
    unsigned ulo, uhi;
    asm("mov.b64 {%0, %1}, %2;" : "=r"(ulo), "=r"(uhi) : "l"(v));
    lo = __uint_as_float(ulo);
    hi = __uint_as_float(uhi);
}

// ---------------------------------------------------------------------------
// CSR build kernels
// ---------------------------------------------------------------------------
__global__ void csr_zero_kernel() {
    int i = blockIdx.x * blockDim.x + threadIdx.x;
    if (i < NN) g_cnt[i] = 0;
}
__global__ void csr_count_kernel(const int* __restrict__ dstv) {
    int e = blockIdx.x * blockDim.x + threadIdx.x;
    if (e < EE) atomicAdd(&g_cnt[dstv[e]], 1);
}
__global__ void csr_scan_kernel() {
    __shared__ int part[1024];
    const int CH = (NN + 1023) / 1024;
    int t = threadIdx.x;
    int start = t * CH;
    int sum = 0;
    for (int i = 0; i < CH; i++) {
        int idx = start + i;
        if (idx < NN) sum += g_cnt[idx];
    }
    part[t] = sum;
    __syncthreads();
    for (int o = 1; o < 1024; o <<= 1) {
        int v = (t >= o) ? part[t - o] : 0;
        __syncthreads();
        part[t] += v;
        __syncthreads();
    }
    int run = part[t] - sum;
    for (int i = 0; i < CH; i++) {
        int idx = start + i;
        if (idx < NN) {
            g_off[idx] = run;
            g_cur[idx] = run;
            run += g_cnt[idx];
        }
    }
    if (t == 0) g_off[NN] = EE;
}
__global__ void csr_fill_kernel(const int* __restrict__ dstv) {
    int e = blockIdx.x * blockDim.x + threadIdx.x;
    if (e < EE) {
        int pos = atomicAdd(&g_cur[dstv[e]], 1);
        g_eid[pos] = e;
    }
}
// Permute payload into CSR order, float4-wide.
__global__ void csr_permute_kernel(const float* __restrict__ attr,
                                   const int* __restrict__ src) {
    int idx = blockIdx.x * blockDim.x + threadIdx.x;   // EE*4 threads
    if (idx >= EE * 4) return;
    int pos = idx >> 2, c4 = idx & 3;
    int e = g_eid[pos];
    float4 v = __ldg((const float4*)&attr[(size_t)e * 16 + c4 * 4]);
    *(float4*)&g_attrs[(size_t)pos * 16 + c4 * 4] = v;
    if (c4 == 0) g_srcs[pos] = __ldg(&src[e]);
}

// ---------------------------------------------------------------------------
// Gather-based edge aggregation: warp per node.
//   agg[n] = x[n] + sum_{e: dst=n} relu(x[src[e]] + attr[e]@eW + eb)
// attrs read with uniform (warp-broadcast) LDG.128; MLP uses f32x2 packed FMA.
// x[src] rows double-prefetched 2-wide.
// ---------------------------------------------------------------------------
template <int D>
__global__ __launch_bounds__(128)
void gather_kernel(const float* __restrict__ x, int ldx,
                   const float* __restrict__ eW,
                   const float* __restrict__ eb,
                   float* __restrict__ agg) {
    constexpr int C = D / 32;                 // floats per lane (2 or 4)
    constexpr int P = C / 2;                  // f32x2 pairs per lane (1 or 2)
    const int lane = threadIdx.x & 31;
    int n = (blockIdx.x * blockDim.x + threadIdx.x) >> 5;
    if (n >= NN) return;

    // packed weights: wp[k*P+p] = {eW[k][lane*C+2p], eW[k][lane*C+2p+1]}
    unsigned long long wp[16 * P];
#pragma unroll
    for (int k = 0; k < 16; k++)
#pragma unroll
        for (int p = 0; p < P; p++) {
            float2 w2 = *(const float2*)&eW[k * D + lane * C + 2 * p];
            wp[k * P + p] = packf2(w2.x, w2.y);
        }
    unsigned long long ebp[P];
#pragma unroll
    for (int p = 0; p < P; p++) {
        float2 b2 = *(const float2*)&eb[lane * C + 2 * p];
        ebp[p] = packf2(b2.x, b2.y);
    }

    float acc[C];
    if constexpr (C == 4) {
        float4 xv = *(const float4*)&x[(size_t)n * ldx + lane * 4];
        acc[0] = xv.x; acc[1] = xv.y; acc[2] = xv.z; acc[3] = xv.w;
    } else {
        float2 xv = *(const float2*)&x[(size_t)n * ldx + lane * 2];
        acc[0] = xv.x; acc[1] = xv.y;
    }

    const int i1 = g_off[n + 1];
    int i0 = g_off[n];

    float xr0[C], xr1[C], nxr0[C], nxr1[C];

    auto ld_x = [&](int pos, float (&xr)[C]) {
        if (pos < i1) {
            int s = __ldg(&g_srcs[pos]);
            if constexpr (C == 4) {
                float4 v = *(const float4*)&x[(size_t)s * ldx + lane * 4];
                xr[0] = v.x; xr[1] = v.y; xr[2] = v.z; xr[3] = v.w;
            } else {
                float2 v = *(const float2*)&x[(size_t)s * ldx + lane * 2];
                xr[0] = v.x; xr[1] = v.y;
            }
        }
    };

    // edge MLP with uniform attr loads + f32x2 FMA; accumulates into acc
    auto process = [&](int pos, const float (&xr)[C]) {
        const float4* ap = (const float4*)&g_attrs[(size_t)pos * 16];
        float4 A0 = __ldg(ap + 0);
        float4 A1 = __ldg(ap + 1);
        float4 A2 = __ldg(ap + 2);
        float4 A3 = __ldg(ap + 3);
        unsigned long long e[P];
#pragma unroll
        for (int p = 0; p < P; p++) e[p] = ebp[p];
        float av[16] = {A0.x, A0.y, A0.z, A0.w, A1.x, A1.y, A1.z, A1.w,
                        A2.x, A2.y, A2.z, A2.w, A3.x, A3.y, A3.z, A3.w};
#pragma unroll
        for (int k = 0; k < 16; k++) {
            unsigned long long av2 = dupf2(av[k]);
#pragma unroll
            for (int p = 0; p < P; p++) fma2(e[p], av2, wp[k * P + p]);
        }
#pragma unroll
        for (int p = 0; p < P; p++) {
            float lo, hi;
            unpackf2(e[p], lo, hi);
            float m0 = xr[2 * p] + lo;
            float m1 = xr[2 * p + 1] + hi;
            acc[2 * p] += m0 > 0.f ? m0 : 0.f;
            acc[2 * p + 1] += m1 > 0.f ? m1 : 0.f;
        }
    };

    if (i0 < i1) {
        ld_x(i0, xr0);
        ld_x(i0 + 1, xr1);
        for (int base = i0; base < i1; base += 2) {
            ld_x(base + 2, nxr0);
            ld_x(base + 3, nxr1);
            process(base, xr0);
            if (base + 1 < i1) process(base + 1, xr1);
#pragma unroll
            for (int c = 0; c < C; c++) { xr0[c] = nxr0[c]; xr1[c] = nxr1[c]; }
        }
    }

    if constexpr (C == 4) {
        *(float4*)&g_agg[(size_t)n * D + lane * 4] =
            make_float4(acc[0], acc[1], acc[2], acc[3]);
    } else {
        *(float2*)&g_agg[(size_t)n * D + lane * 2] = make_float2(acc[0], acc[1]);
    }
}

// ---------------------------------------------------------------------------
// Split-bf16 tensor-core GEMM: C = act(scale(A[N,K] @ B[K,M] + bias))
// ---------------------------------------------------------------------------
__device__ __forceinline__ void mma_bf16(float* acc, const unsigned* a, const unsigned* b) {
    asm volatile(
        "mma.sync.aligned.m16n8k16.row.col.f32.bf16.bf16.f32 "
        "{%0,%1,%2,%3}, {%4,%5,%6,%7}, {%8,%9}, {%0,%1,%2,%3};"
        : "+f"(acc[0]), "+f"(acc[1]), "+f"(acc[2]), "+f"(acc[3])
        : "r"(a[0]), "r"(a[1]), "r"(a[2]), "r"(a[3]), "r"(b[0]), "r"(b[1]));
}

__device__ __forceinline__ unsigned pack_bf16(float lo, float hi) {
    __nv_bfloat162 h = __floats2bfloat162_rn(lo, hi);
    return *(unsigned*)&h;
}

template <int ACT>
__global__ __launch_bounds__(256)
void bf16_gemm(const float* __restrict__ A, int lda,
               const float* __restrict__ B,
               const float* __restrict__ bias,
               const float* __restrict__ gamma,
               const float* __restrict__ beta,
               float* __restrict__ Cmat, int ldc,
               int Nrows, int K, int M, float bn_inv) {
    __shared__ unsigned sAh[128][9];
    __shared__ unsigned sAl[128][9];
    __shared__ unsigned sBh[128][9];
    __shared__ unsigned sBl[128][9];

    const int tid = threadIdx.x;
    const int lane = tid & 31;
    const int wid = tid >> 5;
    const int wm = (wid & 1) * 64;
    const int wn = (wid >> 1) * 32;
    const int row0 = blockIdx.y * 128;
    const int col0 = blockIdx.x * 128;

    float acc[16][4];
#pragma unroll
    for (int i = 0; i < 16; i++)
#pragma unroll
        for (int j = 0; j < 4; j++) acc[i][j] = 0.f;

    float4 ga[2];
    float2 gbe[2], gbo[2];

    auto load_tile = [&](int k0) {
#pragma unroll
        for (int j = 0; j < 2; j++) {
            int idx = j * 256 + tid;
            int m = idx >> 2, kk = (idx & 3) << 2;
            int r = row0 + m;
            ga[j] = make_float4(0.f, 0.f, 0.f, 0.f);
            if (r < Nrows) ga[j] = *(const float4*)&A[(size_t)r * lda + k0 + kk];
            int n = (idx & 63) << 1, kp = idx >> 6;
            gbe[j] = *(const float2*)&B[(size_t)(k0 + 2 * kp) * M + col0 + n];
            gbo[j] = *(const float2*)&B[(size_t)(k0 + 2 * kp + 1) * M + col0 + n];
        }
    };

    load_tile(0);

    for (int k0 = 0; k0 < K; k0 += 16) {
        __syncthreads();
#pragma unroll
        for (int j = 0; j < 2; j++) {
            int idx = j * 256 + tid;
            int m = idx >> 2, kp = (idx & 3) << 1;
            float4 v = ga[j];
            float hx = __bfloat162float(__float2bfloat16(v.x));
            float hy = __bfloat162float(__float2bfloat16(v.y));
            float hz = __bfloat162float(__float2bfloat16(v.z));
            float hw = __bfloat162float(__float2bfloat16(v.w));
            sAh[m][kp]     = pack_bf16(hx, hy);
            sAh[m][kp + 1] = pack_bf16(hz, hw);
            sAl[m][kp]     = pack_bf16(v.x - hx, v.y - hy);
            sAl[m][kp + 1] = pack_bf16(v.z - hz, v.w - hw);

            int n = (idx & 63) << 1, bkp = idx >> 6;
            float2 e = gbe[j], o = gbo[j];
            float hex = __bfloat162float(__float2bfloat16(e.x));
            float hox = __bfloat162float(__float2bfloat16(o.x));
            float hey = __bfloat162float(__float2bfloat16(e.y));
            float hoy = __bfloat162float(__float2bfloat16(o.y));
            sBh[n][bkp]     = pack_bf16(hex, hox);
            sBl[n][bkp]     = pack_bf16(e.x - hex, o.x - hox);
            sBh[n + 1][bkp] = pack_bf16(hey, hoy);
            sBl[n + 1][bkp] = pack_bf16(e.y - hey, o.y - hoy);
        }
        __syncthreads();

        if (k0 + 16 < K) load_tile(k0 + 16);

        unsigned af[4][4], bh[4][2], bl[4][2];
        const int ar = lane >> 2, ak = lane & 3;
#pragma unroll
        for (int i = 0; i < 4; i++) {
            int m = wm + i * 16 + ar;
            af[i][0] = sAh[m][ak];
            af[i][1] = sAh[m + 8][ak];
            af[i][2] = sAh[m][ak + 4];
            af[i][3] = sAh[m + 8][ak + 4];
        }
#pragma unroll
        for (int j = 0; j < 4; j++) {
            int nn = wn + j * 8 + (lane >> 2);
            bh[j][0] = sBh[nn][lane & 3];
            bh[j][1] = sBh[nn][(lane & 3) + 4];
            bl[j][0] = sBl[nn][lane & 3];
            bl[j][1] = sBl[nn][(lane & 3) + 4];
        }
#pragma unroll
        for (int i = 0; i < 4; i++)
#pragma unroll
            for (int j = 0; j < 4; j++) mma_bf16(acc[i * 4 + j], af[i], bh[j]);
#pragma unroll
        for (int i = 0; i < 4; i++)
#pragma unroll
            for (int j = 0; j < 4; j++) mma_bf16(acc[i * 4 + j], af[i], bl[j]);
#pragma unroll
        for (int i = 0; i < 4; i++) {
            int m = wm + i * 16 + ar;
            af[i][0] = sAl[m][ak];
            af[i][1] = sAl[m + 8][ak];
            af[i][2] = sAl[m][ak + 4];
            af[i][3] = sAl[m + 8][ak + 4];
        }
#pragma unroll
        for (int i = 0; i < 4; i++)
#pragma unroll
            for (int j = 0; j < 4; j++) mma_bf16(acc[i * 4 + j], af[i], bh[j]);
    }

    // epilogue
#pragma unroll
    for (int i = 0; i < 4; i++) {
#pragma unroll
        for (int j = 0; j < 4; j++) {
            int r = row0 + wm + i * 16 + (lane >> 2);
            int c = col0 + wn + j * 8 + (lane & 3) * 2;
            float* ap = acc[i * 4 + j];
#pragma unroll
            for (int h = 0; h < 2; h++) {
                int rr = r + h * 8;
                if (rr >= Nrows) continue;
                float v0 = ap[h * 2 + 0] + bias[c];
                float v1 = ap[h * 2 + 1] + bias[c + 1];
                if (gamma != nullptr) {
                    v0 = gamma[c] * (v0 * bn_inv) + beta[c];
                    v1 = gamma[c + 1] * (v1 * bn_inv) + beta[c + 1];
                }
                if (ACT == 1) { v0 = leaky1(v0); v1 = leaky1(v1); }
                else if (ACT == 2) { v0 = dleaky(v0); v1 = dleaky(v1); }
                *(float2*)&Cmat[(size_t)rr * ldc + c] = make_float2(v0, v1);
            }
        }
    }
}

// ---------------------------------------------------------------------------
// Pooling
// ---------------------------------------------------------------------------
__global__ void zero_pool_kernel() {
    int idx = blockIdx.x * blockDim.x + threadIdx.x;
    if (idx < NMOL * 128 / 4)
        *(float4*)&g_pool[idx * 4] = make_float4(0.f, 0.f, 0.f, 0.f);
}

__global__ void pool_kernel(const int* __restrict__ batch) {
    int idx = blockIdx.x * blockDim.x + threadIdx.x;
    int n = idx >> 5;
    if (n >= NN) return;
    int c4 = (idx & 31) << 2;
    float4 v = *(const float4*)&g_HS[(size_t)n * HSW + 384 + c4];
    float* p = g_pool + (size_t)batch[n] * 128 + c4;
    asm volatile("red.global.add.v4.f32 [%0], {%1,%2,%3,%4};"
                 :: "l"(p), "f"(v.x), "f"(v.y), "f"(v.z), "f"(v.w) : "memory");
}

__global__ void bcast_kernel(const int* __restrict__ batch) {
    int idx = blockIdx.x * blockDim.x + threadIdx.x;
    int n = idx >> 5;
    if (n >= NN) return;
    int c4 = (idx & 31) << 2;
    float4 v = *(const float4*)&g_pool[(size_t)batch[n] * 128 + c4];
    *(float4*)&g_HS[(size_t)n * HSW + 512 + c4] = v;
}

// ---------------------------------------------------------------------------
// Final: out[n] = sigmoid(Z1[n,:] . fW + fb)
// ---------------------------------------------------------------------------
__global__ void final_kernel(const float* __restrict__ Z,
                             const float* __restrict__ fW,
                             const float* __restrict__ fb,
                             float* __restrict__ out) {
    int idx = blockIdx.x * blockDim.x + threadIdx.x;
    int n = idx >> 5;
    if (n >= NN) return;
    int lane = idx & 31;
    float s = 0.f;
#pragma unroll
    for (int j = lane; j < CLSD; j += 32)
        s = fmaf(Z[(size_t)n * CLSD + j], fW[j], s);
#pragma unroll
    for (int o = 16; o; o >>= 1) s += __shfl_xor_sync(0xffffffffu, s, o);
    if (lane == 0) {
        float z = s + fb[0];
        out[n] = 1.f / (1.f + expf(-z));
    }
}

// ---------------------------------------------------------------------------
// Launch
// ---------------------------------------------------------------------------
extern "C" void kernel_launch(void* const* d_in, const int* in_sizes, int n_in,
                              void* d_out, int out_size) {
    const float* x    = (const float*)d_in[0];
    const int*   ei   = (const int*)d_in[1];
    const float* attr = (const float*)d_in[2];
    const int*   batch= (const int*)d_in[3];
    const float* c1W  = (const float*)d_in[4];
    const float* c1b  = (const float*)d_in[5];
    const float* c1g  = (const float*)d_in[6];
    const float* c1be = (const float*)d_in[7];
    const float* c1eW = (const float*)d_in[8];
    const float* c1eb = (const float*)d_in[9];
    const float* cW   = (const float*)d_in[10];
    const float* cb   = (const float*)d_in[11];
    const float* cg   = (const float*)d_in[12];
    const float* cbe  = (const float*)d_in[13];
    const float* ceW  = (const float*)d_in[14];
    const float* ceb  = (const float*)d_in[15];
    const float* k1W  = (const float*)d_in[16];
    const float* k1b  = (const float*)d_in[17];
    const float* kW   = (const float*)d_in[18];
    const float* kb   = (const float*)d_in[19];
    const float* fW   = (const float*)d_in[20];
    const float* fb   = (const float*)d_in[21];
    float* out = (float*)d_out;

    const int* srcp = ei;
    const int* dstp = ei + EE;

    const float bn_inv = (float)(1.0 / (double)((float)sqrt(1.0 + 1e-5)));

    float *agg, *h0, *HS, *z1, *z2;
    cudaGetSymbolAddress((void**)&agg, g_agg);
    cudaGetSymbolAddress((void**)&h0,  g_h0);
    cudaGetSymbolAddress((void**)&HS,  g_HS);
    cudaGetSymbolAddress((void**)&z1,  g_z1);
    cudaGetSymbolAddress((void**)&z2,  g_z2);

    // ---- CSR build + payload permute (once per call) ----
    csr_zero_kernel<<<(NN + 255) / 256, 256>>>();
    csr_count_kernel<<<(EE + 255) / 256, 256>>>(dstp);
    csr_scan_kernel<<<1, 1024>>>();
    csr_fill_kernel<<<(EE + 255) / 256, 256>>>(dstp);
    csr_permute_kernel<<<(EE * 4 + 255) / 256, 256>>>(attr, srcp);

    const int GATHER_BLOCKS = (NN * 32 + 127) / 128;

    // ---- conv1 (64 -> 128) ----
    {
        gather_kernel<64><<<GATHER_BLOCKS, 128>>>(x, INRR, c1eW, c1eb, agg);
        dim3 grid(1, (NN + 127) / 128);
        bf16_gemm<2><<<grid, 256>>>(agg, 64, c1W, c1b, c1g, c1be,
                                    h0, 128, NN, 64, 128, bn_inv);
    }

    // ---- conv loop (4 layers, 128 -> 128), outputs into HS cols i*128 ----
    for (int i = 0; i < 4; i++) {
        const float* inPtr = (i == 0) ? h0 : (HS + (size_t)(i - 1) * 128);
        int ldin = (i == 0) ? 128 : HSW;
        gather_kernel<128><<<GATHER_BLOCKS, 128>>>(inPtr, ldin,
                                                   ceW + (size_t)i * EDD * OUTD,
                                                   ceb + (size_t)i * OUTD, agg);
        dim3 grid(1, (NN + 127) / 128);
        bf16_gemm<2><<<grid, 256>>>(agg, 128,
                                    cW + (size_t)i * OUTD * OUTD,
                                    cb + (size_t)i * OUTD,
                                    cg + (size_t)i * OUTD,
                                    cbe + (size_t)i * OUTD,
                                    HS + (size_t)i * 128, HSW,
                                    NN, 128, 128, bn_inv);
    }

    // ---- global_add_pool + broadcast ----
    zero_pool_kernel<<<(NMOL * 128 / 4 + 255) / 256, 256>>>();
    pool_kernel<<<(NN * 32 + 255) / 256, 256>>>(batch);
    bcast_kernel<<<(NN * 32 + 255) / 256, 256>>>(batch);

    // ---- classifier ----
    {
        dim3 grid1(CLSD / 128, (NN + 127) / 128);
        bf16_gemm<0><<<grid1, 256>>>(HS, HSW, k1W, k1b, nullptr, nullptr,
                                     z1, CLSD, NN, HSW, CLSD, bn_inv);
        bf16_gemm<1><<<grid1, 256>>>(z1, CLSD, kW, kb, nullptr, nullptr,
                                     z2, CLSD, NN, CLSD, CLSD, bn_inv);
        bf16_gemm<1><<<grid1, 256>>>(z2, CLSD, kW + CLSD * CLSD, kb + CLSD,
                                     nullptr, nullptr,
                                     z1, CLSD, NN, CLSD, CLSD, bn_inv);
    }

    // ---- final dot + sigmoid ----
    final_kernel<<<(NN * 32 + 255) / 256, 256>>>(z1, fW, fb, out);
}